// round 3
// baseline (speedup 1.0000x reference)
#include <cuda_runtime.h>
#include <math.h>

#define NN    10000
#define NE    120000
#define IND   128
#define HDIM  256
#define H1    8
#define D1    32
#define H2    1
#define D2    32

// ---------------- scratch (device globals; no allocations) ----------------
__device__ float    g_hh0  [NN*HDIM];
__device__ float    g_feat1[NN*HDIM];
__device__ float    g_rst1 [NN*HDIM];
__device__ float    g_hh1  [NN*HDIM];
__device__ float    g_el1  [NN*H1];
__device__ float    g_er1  [NN*H1];
__device__ unsigned g_max1 [NN*H1];
__device__ float    g_sum1 [NN*H1];
__device__ float    g_feat2[NN*D2];
__device__ float    g_rst2 [NN*D2];
__device__ float    g_el2  [NN];
__device__ float    g_er2  [NN];
__device__ unsigned g_max2 [NN];
__device__ float    g_sum2 [NN];
__device__ float    g_bnsum1[HDIM];
__device__ float    g_bnsq1 [HDIM];
__device__ float    g_bnsum2[D2];
__device__ float    g_bnsq2 [D2];

// order-preserving float<->uint for atomicMax on signed floats
__device__ __forceinline__ unsigned f2ord(float f) {
    unsigned u = __float_as_uint(f);
    return (u & 0x80000000u) ? ~u : (u | 0x80000000u);
}
__device__ __forceinline__ float ord2f(unsigned u) {
    return (u & 0x80000000u) ? __uint_as_float(u & 0x7FFFFFFFu)
                             : __uint_as_float(~u);
}

// ---------------- fp32 tiled SGEMM ----------------
template<int BM, int BN, int BK, int TM, int TN, bool BIAS>
__global__ void sgemm(int M, int N, int K,
                      const float* __restrict__ A,
                      const float* __restrict__ B,
                      const float* __restrict__ bias,
                      float* __restrict__ C) {
    __shared__ float As[BK][BM];
    __shared__ float Bs[BK][BN];
    const int NT = (BM/TM)*(BN/TN);
    int tid = threadIdx.x;
    int tx  = tid % (BN/TN);
    int ty  = tid / (BN/TN);
    int bm0 = blockIdx.y * BM;
    int bn0 = blockIdx.x * BN;

    float acc[TM][TN];
    #pragma unroll
    for (int i = 0; i < TM; i++)
        #pragma unroll
        for (int j = 0; j < TN; j++) acc[i][j] = 0.f;

    for (int k0 = 0; k0 < K; k0 += BK) {
        for (int i = tid; i < BM*BK; i += NT) {
            int r = i / BK, c = i % BK;
            int gr = bm0 + r;
            As[c][r] = (gr < M) ? A[(long)gr*K + k0 + c] : 0.f;
        }
        for (int i = tid; i < BK*BN; i += NT) {
            int r = i / BN, c = i % BN;
            Bs[r][c] = B[(long)(k0 + r)*N + bn0 + c];  // N % BN == 0, K % BK == 0
        }
        __syncthreads();
        #pragma unroll
        for (int kk = 0; kk < BK; kk++) {
            float a[TM], b[TN];
            #pragma unroll
            for (int i = 0; i < TM; i++) a[i] = As[kk][ty*TM + i];
            #pragma unroll
            for (int j = 0; j < TN; j++) b[j] = Bs[kk][tx*TN + j];
            #pragma unroll
            for (int i = 0; i < TM; i++)
                #pragma unroll
                for (int j = 0; j < TN; j++) acc[i][j] += a[i]*b[j];
        }
        __syncthreads();
    }
    #pragma unroll
    for (int i = 0; i < TM; i++) {
        int gr = bm0 + ty*TM + i;
        if (gr < M) {
            #pragma unroll
            for (int j = 0; j < TN; j++) {
                int gc = bn0 + tx*TN + j;
                float v = acc[i][j];
                if (BIAS) v += bias[gc];
                C[(long)gr*N + gc] = v;
            }
        }
    }
}

// ---------------- attention coefficients: el/er per (node, head) ----------------
__global__ void attn_coeff(const float* __restrict__ feat,
                           const float* __restrict__ al,
                           const float* __restrict__ ar,
                           float* __restrict__ el, float* __restrict__ er,
                           int n, int H, int D) {
    int idx = blockIdx.x * blockDim.x + threadIdx.x;
    if (idx >= n * H) return;
    int h = idx % H;
    float e1 = 0.f, e2 = 0.f;
    const float* f = feat + (long)idx * D;   // row layout [n, H, D] -> (n*H+h)*D
    const float* wl = al + h * D;
    const float* wr = ar + h * D;
    #pragma unroll 8
    for (int d = 0; d < D; d++) {
        float v = f[d];
        e1 += v * wl[d];
        e2 += v * wr[d];
    }
    el[idx] = e1;
    er[idx] = e2;
}

// ---------------- edge pass 1: segment max of leaky-relu logits ----------------
__global__ void edge_max(const int* __restrict__ src, const int* __restrict__ dst,
                         const float* __restrict__ el, const float* __restrict__ er,
                         unsigned* __restrict__ segmax, int E, int H) {
    int idx = blockIdx.x * blockDim.x + threadIdx.x;
    if (idx >= E * H) return;
    int e = idx / H, h = idx % H;
    int d = dst[e];
    float l = el[src[e]*H + h] + er[d*H + h];
    l = (l >= 0.f) ? l : 0.2f * l;
    atomicMax(&segmax[d*H + h], f2ord(l));
}

// ---------------- edge pass 2: segment sum of exp(logit - max) ----------------
__global__ void edge_expsum(const int* __restrict__ src, const int* __restrict__ dst,
                            const float* __restrict__ el, const float* __restrict__ er,
                            const unsigned* __restrict__ segmax,
                            float* __restrict__ segsum, int E, int H) {
    int idx = blockIdx.x * blockDim.x + threadIdx.x;
    if (idx >= E * H) return;
    int e = idx / H, h = idx % H;
    int d = dst[e];
    float l = el[src[e]*H + h] + er[d*H + h];
    l = (l >= 0.f) ? l : 0.2f * l;
    float m = ord2f(segmax[d*H + h]);
    atomicAdd(&segsum[d*H + h], expf(l - m));
}

// ---------------- edge pass 3: scatter alpha * feat[src] into rst[dst] ----------------
// one warp per edge, 32 lanes = 32 channels of each head
__global__ void edge_scatter(const int* __restrict__ src, const int* __restrict__ dst,
                             const float* __restrict__ el, const float* __restrict__ er,
                             const unsigned* __restrict__ segmax,
                             const float* __restrict__ segsum,
                             const float* __restrict__ feat,
                             float* __restrict__ rst, int E, int H) {
    int w = (blockIdx.x * blockDim.x + threadIdx.x) >> 5;
    int lane = threadIdx.x & 31;
    if (w >= E) return;
    int sn = src[w], dn = dst[w];
    #pragma unroll
    for (int h = 0; h < 8; h++) {
        if (h >= H) break;
        float l = el[sn*H + h] + er[dn*H + h];
        l = (l >= 0.f) ? l : 0.2f * l;
        float m = ord2f(segmax[dn*H + h]);
        float a = expf(l - m) / (segsum[dn*H + h] + 1e-16f);
        float v = feat[((long)sn*H + h)*32 + lane];           // D == 32 both layers
        atomicAdd(&rst[((long)dn*H + h)*32 + lane], a * v);
    }
}

// ---------------- BN batch stats: per-channel sum & sumsq ----------------
__global__ void bn_stats(const float* __restrict__ x,
                         float* __restrict__ gsum, float* __restrict__ gsq,
                         int n, int C) {
    int tid = threadIdx.x;
    int c  = tid % C;
    int rl = tid / C;
    int L  = blockDim.x / C;
    int rows = (n + gridDim.x - 1) / gridDim.x;
    int r0 = blockIdx.x * rows;
    int r1 = min(n, r0 + rows);
    float s = 0.f, q = 0.f;
    for (int r = r0 + rl; r < r1; r += L) {
        float v = x[(long)r*C + c];
        s += v; q += v*v;
    }
    __shared__ float ss[256], sq[256];
    ss[tid] = s; sq[tid] = q;
    __syncthreads();
    if (rl == 0) {
        for (int l = 1; l < L; l++) { s += ss[l*C + c]; q += sq[l*C + c]; }
        atomicAdd(&gsum[c], s);
        atomicAdd(&gsq[c],  q);
    }
}

// ---------------- BN apply + ELU (+ optional residual) ----------------
__global__ void bn_apply(const float* __restrict__ x,
                         const float* __restrict__ gsum, const float* __restrict__ gsq,
                         const float* __restrict__ g, const float* __restrict__ b,
                         const float* __restrict__ resid,
                         float* __restrict__ out, int n, int C) {
    int idx = blockIdx.x * blockDim.x + threadIdx.x;
    if (idx >= n * C) return;
    int c = idx % C;
    float inv_n = 1.f / (float)n;
    float mu  = gsum[c] * inv_n;
    float var = gsq[c] * inv_n - mu*mu;
    float y = g[c] * (x[idx] - mu) * rsqrtf(var + 1e-5f) + b[c];
    y = (y > 0.f) ? y : expm1f(y);
    if (resid) y += resid[idx];
    out[idx] = y;
}

// ---------------- host launch ----------------
static inline void* sym(const void* s) {
    void* p = nullptr;
    cudaGetSymbolAddress(&p, s);
    return p;
}

extern "C" void kernel_launch(void* const* d_in, const int* in_sizes, int n_in,
                              void* d_out, int out_size) {
    const float* h     = (const float*)d_in[0];
    const int*   src   = (const int*)  d_in[2];
    const int*   dst   = (const int*)  d_in[3];
    const float* W_emb = (const float*)d_in[4];
    const float* b_emb = (const float*)d_in[5];
    const float* fc1   = (const float*)d_in[18];
    const float* al1   = (const float*)d_in[19];
    const float* ar1   = (const float*)d_in[20];
    const float* g1    = (const float*)d_in[21];
    const float* b1    = (const float*)d_in[22];
    const float* fc2   = (const float*)d_in[23];
    const float* al2   = (const float*)d_in[24];
    const float* ar2   = (const float*)d_in[25];
    const float* g2    = (const float*)d_in[26];
    const float* b2    = (const float*)d_in[27];
    float* out = (float*)d_out;

    float*    hh0   = (float*)   sym(g_hh0);
    float*    feat1 = (float*)   sym(g_feat1);
    float*    rst1  = (float*)   sym(g_rst1);
    float*    hh1   = (float*)   sym(g_hh1);
    float*    el1   = (float*)   sym(g_el1);
    float*    er1   = (float*)   sym(g_er1);
    unsigned* max1  = (unsigned*)sym(g_max1);
    float*    sum1  = (float*)   sym(g_sum1);
    float*    feat2 = (float*)   sym(g_feat2);
    float*    rst2  = (float*)   sym(g_rst2);
    float*    el2   = (float*)   sym(g_el2);
    float*    er2   = (float*)   sym(g_er2);
    unsigned* max2  = (unsigned*)sym(g_max2);
    float*    sum2  = (float*)   sym(g_sum2);
    float*    bnsum1= (float*)   sym(g_bnsum1);
    float*    bnsq1 = (float*)   sym(g_bnsq1);
    float*    bnsum2= (float*)   sym(g_bnsum2);
    float*    bnsq2 = (float*)   sym(g_bnsq2);

    // zero accumulators every call (graph replays must be deterministic)
    cudaMemsetAsync(rst1,  0, sizeof(float)*NN*HDIM);
    cudaMemsetAsync(max1,  0, sizeof(unsigned)*NN*H1);   // ord-encoding: 0 == below any finite value
    cudaMemsetAsync(sum1,  0, sizeof(float)*NN*H1);
    cudaMemsetAsync(rst2,  0, sizeof(float)*NN*D2);
    cudaMemsetAsync(max2,  0, sizeof(unsigned)*NN);
    cudaMemsetAsync(sum2,  0, sizeof(float)*NN);
    cudaMemsetAsync(bnsum1,0, sizeof(float)*HDIM);
    cudaMemsetAsync(bnsq1, 0, sizeof(float)*HDIM);
    cudaMemsetAsync(bnsum2,0, sizeof(float)*D2);
    cudaMemsetAsync(bnsq2, 0, sizeof(float)*D2);

    // 1) hh0 = h @ W_emb + b_emb    [10000,128]x[128,256]
    {
        dim3 grid((HDIM + 127)/128, (NN + 127)/128);
        sgemm<128,128,8,8,8,true><<<grid, 256>>>(NN, HDIM, IND, h, W_emb, b_emb, hh0);
    }
    // 2) feat1 = hh0 @ fc1          [10000,256]x[256,256]
    {
        dim3 grid((HDIM + 127)/128, (NN + 127)/128);
        sgemm<128,128,8,8,8,false><<<grid, 256>>>(NN, HDIM, HDIM, hh0, fc1, nullptr, feat1);
    }
    // 3) el1/er1
    attn_coeff<<<(NN*H1 + 255)/256, 256>>>(feat1, al1, ar1, el1, er1, NN, H1, D1);
    // 4) segment softmax (layer 1)
    edge_max   <<<(NE*H1 + 255)/256, 256>>>(src, dst, el1, er1, max1, NE, H1);
    edge_expsum<<<(NE*H1 + 255)/256, 256>>>(src, dst, el1, er1, max1, sum1, NE, H1);
    edge_scatter<<<(NE*32 + 255)/256, 256>>>(src, dst, el1, er1, max1, sum1, feat1, rst1, NE, H1);
    // 5) BN + ELU + residual -> hh1
    bn_stats<<<157, 256>>>(rst1, bnsum1, bnsq1, NN, HDIM);
    bn_apply<<<(NN*HDIM + 255)/256, 256>>>(rst1, bnsum1, bnsq1, g1, b1, hh0, hh1, NN, HDIM);

    // 6) feat2 = hh1 @ fc2          [10000,256]x[256,32]
    {
        dim3 grid(1, (NN + 127)/128);
        sgemm<128,32,8,8,2,false><<<grid, 256>>>(NN, D2, HDIM, hh1, fc2, nullptr, feat2);
    }
    // 7) el2/er2
    attn_coeff<<<(NN + 255)/256, 256>>>(feat2, al2, ar2, el2, er2, NN, H2, D2);
    // 8) segment softmax (layer 2)
    edge_max   <<<(NE + 255)/256, 256>>>(src, dst, el2, er2, max2, NE, H2);
    edge_expsum<<<(NE + 255)/256, 256>>>(src, dst, el2, er2, max2, sum2, NE, H2);
    edge_scatter<<<(NE*32 + 255)/256, 256>>>(src, dst, el2, er2, max2, sum2, feat2, rst2, NE, H2);
    // 9) BN + ELU -> out
    bn_stats<<<157, 256>>>(rst2, bnsum2, bnsq2, NN, D2);
    bn_apply<<<(NN*D2 + 255)/256, 256>>>(rst2, bnsum2, bnsq2, g2, b2, nullptr, out, NN, D2);

    (void)in_sizes; (void)n_in; (void)out_size;
}

// round 4
// speedup vs baseline: 2.1404x; 2.1404x over previous
#include <cuda_runtime.h>
#include <math.h>

#define NN    10000
#define NE    120000
#define IND   128
#define HDIM  256
#define H1    8
#define D1    32
#define H2    1
#define D2    32

// ---------------- scratch (device globals; no allocations) ----------------
__device__ float    g_hh0  [NN*HDIM];
__device__ float    g_feat1[NN*HDIM];
__device__ float    g_rst1 [NN*HDIM];
__device__ float    g_hh1  [NN*HDIM];
__device__ float    g_el1  [NN*H1];
__device__ float    g_er1  [NN*H1];
__device__ float    g_feat2[NN*D2];
__device__ float    g_rst2 [NN*D2];
__device__ float    g_el2  [NN];
__device__ float    g_er2  [NN];
__device__ float    g_bnsum1[HDIM];
__device__ float    g_bnsq1 [HDIM];
__device__ float    g_bnsum2[D2];
__device__ float    g_bnsq2 [D2];
// CSR by destination
__device__ int      g_deg   [NN];
__device__ int      g_rowptr[NN+1];
__device__ int      g_cursor[NN];
__device__ int      g_eidx  [NE];
// precomputed leaky-relu logits
__device__ float    g_logits1[NE*H1];
__device__ float    g_logits2[NE];

// ---------------- fp32 tiled SGEMM (BK=16, float4 loads) ----------------
template<int BM, int BN, int BK, int TM, int TN, bool BIAS>
__global__ void sgemm(int M, int N, int K,
                      const float* __restrict__ A,
                      const float* __restrict__ B,
                      const float* __restrict__ bias,
                      float* __restrict__ C) {
    __shared__ __align__(16) float As[BK][BM+4];
    __shared__ __align__(16) float Bs[BK][BN];
    const int NT = (BM/TM)*(BN/TN);
    int tid = threadIdx.x;
    int tx  = tid % (BN/TN);
    int ty  = tid / (BN/TN);
    int bm0 = blockIdx.y * BM;
    int bn0 = blockIdx.x * BN;

    float acc[TM][TN];
    #pragma unroll
    for (int i = 0; i < TM; i++)
        #pragma unroll
        for (int j = 0; j < TN; j++) acc[i][j] = 0.f;

    const int AV = BM*BK/4;   // float4 elements in A tile
    const int BV = BK*BN/4;

    for (int k0 = 0; k0 < K; k0 += BK) {
        #pragma unroll
        for (int v = tid; v < AV; v += NT) {
            int r  = v / (BK/4);
            int c4 = (v % (BK/4)) * 4;
            int gr = bm0 + r;
            float4 x = make_float4(0.f,0.f,0.f,0.f);
            if (gr < M) x = *(const float4*)&A[(long)gr*K + k0 + c4];
            As[c4+0][r] = x.x; As[c4+1][r] = x.y;
            As[c4+2][r] = x.z; As[c4+3][r] = x.w;
        }
        #pragma unroll
        for (int v = tid; v < BV; v += NT) {
            int r  = v / (BN/4);
            int c4 = (v % (BN/4)) * 4;
            *(float4*)&Bs[r][c4] = *(const float4*)&B[(long)(k0 + r)*N + bn0 + c4];
        }
        __syncthreads();
        #pragma unroll
        for (int kk = 0; kk < BK; kk++) {
            float a[TM], b[TN];
            #pragma unroll
            for (int i = 0; i < TM; i++) a[i] = As[kk][ty*TM + i];
            #pragma unroll
            for (int j = 0; j < TN; j++) b[j] = Bs[kk][tx*TN + j];
            #pragma unroll
            for (int i = 0; i < TM; i++)
                #pragma unroll
                for (int j = 0; j < TN; j++) acc[i][j] += a[i]*b[j];
        }
        __syncthreads();
    }
    #pragma unroll
    for (int i = 0; i < TM; i++) {
        int gr = bm0 + ty*TM + i;
        if (gr < M) {
            #pragma unroll
            for (int j = 0; j < TN; j++) {
                int gc = bn0 + tx*TN + j;
                float v = acc[i][j];
                if (BIAS) v += bias[gc];
                C[(long)gr*N + gc] = v;
            }
        }
    }
}

// ---------------- CSR construction ----------------
__global__ void csr_count(const int* __restrict__ dst, int* __restrict__ deg, int E) {
    int e = blockIdx.x * blockDim.x + threadIdx.x;
    if (e < E) atomicAdd(&deg[dst[e]], 1);
}

__global__ void csr_scan(const int* __restrict__ deg, int* __restrict__ rowptr) {
    __shared__ int part[1024];
    int tid = threadIdx.x;
    const int PER = (NN + 1023) / 1024;  // 10
    int base = tid * PER;
    int local[PER];
    int s = 0;
    #pragma unroll
    for (int i = 0; i < PER; i++) {
        int idx = base + i;
        local[i] = (idx < NN) ? deg[idx] : 0;
        s += local[i];
    }
    part[tid] = s;
    __syncthreads();
    for (int off = 1; off < 1024; off <<= 1) {
        int v = (tid >= off) ? part[tid - off] : 0;
        __syncthreads();
        part[tid] += v;
        __syncthreads();
    }
    int excl = part[tid] - s;
    #pragma unroll
    for (int i = 0; i < PER; i++) {
        int idx = base + i;
        if (idx < NN) rowptr[idx] = excl;
        excl += local[i];
    }
    if (tid == 1023) rowptr[NN] = excl;
}

__global__ void csr_fill(const int* __restrict__ dst, int* __restrict__ cursor,
                         int* __restrict__ eidx, int E) {
    int e = blockIdx.x * blockDim.x + threadIdx.x;
    if (e >= E) return;
    int p = atomicAdd(&cursor[dst[e]], 1);
    eidx[p] = e;
}

// ---------------- attention coefficients: el/er per (node, head) ----------------
__global__ void attn_coeff(const float* __restrict__ feat,
                           const float* __restrict__ al,
                           const float* __restrict__ ar,
                           float* __restrict__ el, float* __restrict__ er,
                           int n, int H, int D) {
    int idx = blockIdx.x * blockDim.x + threadIdx.x;
    if (idx >= n * H) return;
    int h = idx % H;
    float e1 = 0.f, e2 = 0.f;
    const float* f = feat + (long)idx * D;
    const float* wl = al + h * D;
    const float* wr = ar + h * D;
    #pragma unroll 8
    for (int d = 0; d < D; d++) {
        float v = f[d];
        e1 += v * wl[d];
        e2 += v * wr[d];
    }
    el[idx] = e1;
    er[idx] = e2;
}

__device__ __forceinline__ float leaky(float x) { return (x >= 0.f) ? x : 0.2f * x; }

// ---------------- per-edge leaky-relu logits, layer 1 (8 heads) ----------------
__global__ void edge_logits1(const int* __restrict__ src, const int* __restrict__ dst,
                             const float* __restrict__ el, const float* __restrict__ er,
                             float* __restrict__ out, int E) {
    int e = blockIdx.x * blockDim.x + threadIdx.x;
    if (e >= E) return;
    const float4* lp = (const float4*)(el + (long)src[e]*8);
    const float4* rp = (const float4*)(er + (long)dst[e]*8);
    float4 l0 = lp[0], l1 = lp[1];
    float4 r0 = rp[0], r1 = rp[1];
    float4 o0, o1;
    o0.x = leaky(l0.x + r0.x); o0.y = leaky(l0.y + r0.y);
    o0.z = leaky(l0.z + r0.z); o0.w = leaky(l0.w + r0.w);
    o1.x = leaky(l1.x + r1.x); o1.y = leaky(l1.y + r1.y);
    o1.z = leaky(l1.z + r1.z); o1.w = leaky(l1.w + r1.w);
    float4* op = (float4*)(out + (long)e*8);
    op[0] = o0; op[1] = o1;
}

// ---------------- per-edge logits, layer 2 (1 head) ----------------
__global__ void edge_logits2(const int* __restrict__ src, const int* __restrict__ dst,
                             const float* __restrict__ el, const float* __restrict__ er,
                             float* __restrict__ out, int E) {
    int e = blockIdx.x * blockDim.x + threadIdx.x;
    if (e >= E) return;
    out[e] = leaky(el[src[e]] + er[dst[e]]);
}

// ---------------- gather aggregation, layer 1: warp per node, 8 heads ----------------
__global__ void gat_gather1(const int* __restrict__ rowptr, const int* __restrict__ eidx,
                            const int* __restrict__ src,
                            const float* __restrict__ logits,   // [E,8]
                            const float* __restrict__ feat,     // [N,256]
                            float* __restrict__ rst) {
    int node = blockIdx.x * (blockDim.x >> 5) + (threadIdx.x >> 5);
    int lane = threadIdx.x & 31;
    if (node >= NN) return;
    int s0 = rowptr[node], deg = rowptr[node+1] - s0;

    // pass 1: per-head max
    float m[8];
    #pragma unroll
    for (int h = 0; h < 8; h++) m[h] = -3.4e38f;
    for (int i = lane; i < deg; i += 32) {
        int e = eidx[s0 + i];
        const float4* lp = (const float4*)(logits + (long)e*8);
        float4 a = lp[0], b = lp[1];
        m[0]=fmaxf(m[0],a.x); m[1]=fmaxf(m[1],a.y); m[2]=fmaxf(m[2],a.z); m[3]=fmaxf(m[3],a.w);
        m[4]=fmaxf(m[4],b.x); m[5]=fmaxf(m[5],b.y); m[6]=fmaxf(m[6],b.z); m[7]=fmaxf(m[7],b.w);
    }
    #pragma unroll
    for (int h = 0; h < 8; h++)
        #pragma unroll
        for (int off = 16; off; off >>= 1)
            m[h] = fmaxf(m[h], __shfl_xor_sync(0xffffffffu, m[h], off));

    // pass 2: exp-sum
    float s[8];
    #pragma unroll
    for (int h = 0; h < 8; h++) s[h] = 0.f;
    for (int i = lane; i < deg; i += 32) {
        int e = eidx[s0 + i];
        const float4* lp = (const float4*)(logits + (long)e*8);
        float4 a = lp[0], b = lp[1];
        s[0]+=expf(a.x-m[0]); s[1]+=expf(a.y-m[1]); s[2]+=expf(a.z-m[2]); s[3]+=expf(a.w-m[3]);
        s[4]+=expf(b.x-m[4]); s[5]+=expf(b.y-m[5]); s[6]+=expf(b.z-m[6]); s[7]+=expf(b.w-m[7]);
    }
    #pragma unroll
    for (int h = 0; h < 8; h++) {
        #pragma unroll
        for (int off = 16; off; off >>= 1)
            s[h] += __shfl_xor_sync(0xffffffffu, s[h], off);
        s[h] = 1.f / (s[h] + 1e-16f);
    }

    // pass 3: weighted aggregation (lane = channel within each head)
    float acc[8];
    #pragma unroll
    for (int h = 0; h < 8; h++) acc[h] = 0.f;
    for (int base = 0; base < deg; base += 32) {
        int cnt = min(32, deg - base);
        float al[8]; int sv = 0;
        #pragma unroll
        for (int h = 0; h < 8; h++) al[h] = 0.f;
        if (lane < cnt) {
            int e = eidx[s0 + base + lane];
            sv = src[e];
            const float4* lp = (const float4*)(logits + (long)e*8);
            float4 a = lp[0], b = lp[1];
            al[0]=expf(a.x-m[0])*s[0]; al[1]=expf(a.y-m[1])*s[1];
            al[2]=expf(a.z-m[2])*s[2]; al[3]=expf(a.w-m[3])*s[3];
            al[4]=expf(b.x-m[4])*s[4]; al[5]=expf(b.y-m[5])*s[5];
            al[6]=expf(b.z-m[6])*s[6]; al[7]=expf(b.w-m[7])*s[7];
        }
        for (int j = 0; j < cnt; j++) {
            int sn = __shfl_sync(0xffffffffu, sv, j);
            const float* fp = feat + (long)sn*HDIM + lane;
            #pragma unroll
            for (int h = 0; h < 8; h++) {
                float a = __shfl_sync(0xffffffffu, al[h], j);
                acc[h] = fmaf(a, fp[h*32], acc[h]);
            }
        }
    }
    float* rp = rst + (long)node*HDIM + lane;
    #pragma unroll
    for (int h = 0; h < 8; h++) rp[h*32] = acc[h];
}

// ---------------- gather aggregation, layer 2: warp per node, 1 head ----------------
__global__ void gat_gather2(const int* __restrict__ rowptr, const int* __restrict__ eidx,
                            const int* __restrict__ src,
                            const float* __restrict__ logits,   // [E]
                            const float* __restrict__ feat,     // [N,32]
                            float* __restrict__ rst) {
    int node = blockIdx.x * (blockDim.x >> 5) + (threadIdx.x >> 5);
    int lane = threadIdx.x & 31;
    if (node >= NN) return;
    int s0 = rowptr[node], deg = rowptr[node+1] - s0;

    float m = -3.4e38f;
    for (int i = lane; i < deg; i += 32)
        m = fmaxf(m, logits[eidx[s0 + i]]);
    #pragma unroll
    for (int off = 16; off; off >>= 1)
        m = fmaxf(m, __shfl_xor_sync(0xffffffffu, m, off));

    float s = 0.f;
    for (int i = lane; i < deg; i += 32)
        s += expf(logits[eidx[s0 + i]] - m);
    #pragma unroll
    for (int off = 16; off; off >>= 1)
        s += __shfl_xor_sync(0xffffffffu, s, off);
    float inv = 1.f / (s + 1e-16f);

    float acc = 0.f;
    for (int base = 0; base < deg; base += 32) {
        int cnt = min(32, deg - base);
        float al = 0.f; int sv = 0;
        if (lane < cnt) {
            int e = eidx[s0 + base + lane];
            sv = src[e];
            al = expf(logits[e] - m) * inv;
        }
        for (int j = 0; j < cnt; j++) {
            int sn = __shfl_sync(0xffffffffu, sv, j);
            float a = __shfl_sync(0xffffffffu, al, j);
            acc = fmaf(a, feat[(long)sn*D2 + lane], acc);
        }
    }
    rst[(long)node*D2 + lane] = acc;
}

// ---------------- BN batch stats: per-channel sum & sumsq ----------------
__global__ void bn_stats(const float* __restrict__ x,
                         float* __restrict__ gsum, float* __restrict__ gsq,
                         int n, int C) {
    int tid = threadIdx.x;
    int c  = tid % C;
    int rl = tid / C;
    int L  = blockDim.x / C;
    int rows = (n + gridDim.x - 1) / gridDim.x;
    int r0 = blockIdx.x * rows;
    int r1 = min(n, r0 + rows);
    float s = 0.f, q = 0.f;
    for (int r = r0 + rl; r < r1; r += L) {
        float v = x[(long)r*C + c];
        s += v; q += v*v;
    }
    __shared__ float ss[256], sq[256];
    ss[tid] = s; sq[tid] = q;
    __syncthreads();
    if (rl == 0) {
        for (int l = 1; l < L; l++) { s += ss[l*C + c]; q += sq[l*C + c]; }
        atomicAdd(&gsum[c], s);
        atomicAdd(&gsq[c],  q);
    }
}

// ---------------- BN apply + ELU (+ optional residual) ----------------
__global__ void bn_apply(const float* __restrict__ x,
                         const float* __restrict__ gsum, const float* __restrict__ gsq,
                         const float* __restrict__ g, const float* __restrict__ b,
                         const float* __restrict__ resid,
                         float* __restrict__ out, int n, int C) {
    int idx = blockIdx.x * blockDim.x + threadIdx.x;
    if (idx >= n * C) return;
    int c = idx % C;
    float inv_n = 1.f / (float)n;
    float mu  = gsum[c] * inv_n;
    float var = gsq[c] * inv_n - mu*mu;
    float y = g[c] * (x[idx] - mu) * rsqrtf(var + 1e-5f) + b[c];
    y = (y > 0.f) ? y : expm1f(y);
    if (resid) y += resid[idx];
    out[idx] = y;
}

// ---------------- host launch ----------------
static inline void* sym(const void* s) {
    void* p = nullptr;
    cudaGetSymbolAddress(&p, s);
    return p;
}

extern "C" void kernel_launch(void* const* d_in, const int* in_sizes, int n_in,
                              void* d_out, int out_size) {
    const float* h     = (const float*)d_in[0];
    const int*   src   = (const int*)  d_in[2];
    const int*   dst   = (const int*)  d_in[3];
    const float* W_emb = (const float*)d_in[4];
    const float* b_emb = (const float*)d_in[5];
    const float* fc1   = (const float*)d_in[18];
    const float* al1   = (const float*)d_in[19];
    const float* ar1   = (const float*)d_in[20];
    const float* g1    = (const float*)d_in[21];
    const float* b1    = (const float*)d_in[22];
    const float* fc2   = (const float*)d_in[23];
    const float* al2   = (const float*)d_in[24];
    const float* ar2   = (const float*)d_in[25];
    const float* g2    = (const float*)d_in[26];
    const float* b2    = (const float*)d_in[27];
    float* out = (float*)d_out;

    float* hh0   = (float*)sym(g_hh0);
    float* feat1 = (float*)sym(g_feat1);
    float* rst1  = (float*)sym(g_rst1);
    float* hh1   = (float*)sym(g_hh1);
    float* el1   = (float*)sym(g_el1);
    float* er1   = (float*)sym(g_er1);
    float* feat2 = (float*)sym(g_feat2);
    float* rst2  = (float*)sym(g_rst2);
    float* el2   = (float*)sym(g_el2);
    float* er2   = (float*)sym(g_er2);
    float* bnsum1= (float*)sym(g_bnsum1);
    float* bnsq1 = (float*)sym(g_bnsq1);
    float* bnsum2= (float*)sym(g_bnsum2);
    float* bnsq2 = (float*)sym(g_bnsq2);
    int*   deg   = (int*)  sym(g_deg);
    int*   rowptr= (int*)  sym(g_rowptr);
    int*   cursor= (int*)  sym(g_cursor);
    int*   eidx  = (int*)  sym(g_eidx);
    float* log1  = (float*)sym(g_logits1);
    float* log2  = (float*)sym(g_logits2);

    // zero accumulators (graph replays must be deterministic)
    cudaMemsetAsync(deg,   0, sizeof(int)*NN);
    cudaMemsetAsync(bnsum1,0, sizeof(float)*HDIM);
    cudaMemsetAsync(bnsq1, 0, sizeof(float)*HDIM);
    cudaMemsetAsync(bnsum2,0, sizeof(float)*D2);
    cudaMemsetAsync(bnsq2, 0, sizeof(float)*D2);

    // CSR by destination
    csr_count<<<(NE + 255)/256, 256>>>(dst, deg, NE);
    csr_scan <<<1, 1024>>>(deg, rowptr);
    cudaMemcpyAsync(cursor, rowptr, sizeof(int)*NN, cudaMemcpyDeviceToDevice);
    csr_fill <<<(NE + 255)/256, 256>>>(dst, cursor, eidx, NE);

    // 1) hh0 = h @ W_emb + b_emb    [10000,128]x[128,256]
    {
        dim3 grid(HDIM/128, (NN + 127)/128);
        sgemm<128,128,16,8,8,true><<<grid, 256>>>(NN, HDIM, IND, h, W_emb, b_emb, hh0);
    }
    // 2) feat1 = hh0 @ fc1          [10000,256]x[256,256]
    {
        dim3 grid(HDIM/128, (NN + 127)/128);
        sgemm<128,128,16,8,8,false><<<grid, 256>>>(NN, HDIM, HDIM, hh0, fc1, nullptr, feat1);
    }
    // 3) el/er, per-edge logits
    attn_coeff <<<(NN*H1 + 255)/256, 256>>>(feat1, al1, ar1, el1, er1, NN, H1, D1);
    edge_logits1<<<(NE + 255)/256, 256>>>(src, dst, el1, er1, log1, NE);
    // 4) gather aggregation (no atomics)
    gat_gather1<<<(NN*32 + 255)/256, 256>>>(rowptr, eidx, src, log1, feat1, rst1);
    // 5) BN + ELU + residual -> hh1
    bn_stats<<<157, 256>>>(rst1, bnsum1, bnsq1, NN, HDIM);
    bn_apply<<<(NN*HDIM + 255)/256, 256>>>(rst1, bnsum1, bnsq1, g1, b1, hh0, hh1, NN, HDIM);

    // 6) feat2 = hh1 @ fc2          [10000,256]x[256,32]
    {
        dim3 grid(1, (NN + 127)/128);
        sgemm<128,32,16,8,2,false><<<grid, 256>>>(NN, D2, HDIM, hh1, fc2, nullptr, feat2);
    }
    // 7) layer-2 attention
    attn_coeff <<<(NN + 255)/256, 256>>>(feat2, al2, ar2, el2, er2, NN, H2, D2);
    edge_logits2<<<(NE + 255)/256, 256>>>(src, dst, el2, er2, log2, NE);
    gat_gather2<<<(NN*32 + 255)/256, 256>>>(rowptr, eidx, src, log2, feat2, rst2);
    // 8) BN + ELU -> out
    bn_stats<<<157, 256>>>(rst2, bnsum2, bnsq2, NN, D2);
    bn_apply<<<(NN*D2 + 255)/256, 256>>>(rst2, bnsum2, bnsq2, g2, b2, nullptr, out, NN, D2);

    (void)in_sizes; (void)n_in; (void)out_size;
}

// round 6
// speedup vs baseline: 3.3073x; 1.5452x over previous
#include <cuda_runtime.h>
#include <math.h>
#include <stdint.h>

#define NN    10000
#define NE    120000
#define IND   128
#define HDIM  256
#define H1    8
#define D1    32
#define H2    1
#define D2    32

// ---------------- scratch (device globals; no allocations) ----------------
__device__ float    g_hh0  [NN*HDIM];
__device__ float    g_feat1[NN*HDIM];
__device__ float    g_rst1 [NN*HDIM];
__device__ float    g_hh1  [NN*HDIM];
__device__ float    g_el1  [NN*H1];
__device__ float    g_er1  [NN*H1];
__device__ float    g_feat2[NN*D2];
__device__ float    g_rst2 [NN*D2];
__device__ float    g_el2  [NN];
__device__ float    g_er2  [NN];
__device__ float    g_bnsum1[HDIM];
__device__ float    g_bnsq1 [HDIM];
__device__ float    g_bnsum2[D2];
__device__ float    g_bnsq2 [D2];
// CSR by destination
__device__ int      g_deg   [NN];
__device__ int      g_rowptr[NN+1];
__device__ int      g_cursor[NN];
__device__ int      g_eidx  [NE];
// precomputed leaky-relu logits
__device__ float    g_logits1[NE*H1];
__device__ float    g_logits2[NE];

// ---------------- tf32 helpers ----------------
__device__ __forceinline__ uint32_t f2tf32(float f) {
    uint32_t u;
    asm("cvt.rna.tf32.f32 %0, %1;" : "=r"(u) : "f"(f));
    return u;
}

__device__ __forceinline__ void mma_tf32(float* d, const uint32_t* a, const uint32_t* b) {
    asm volatile(
        "mma.sync.aligned.m16n8k8.row.col.f32.tf32.tf32.f32 "
        "{%0,%1,%2,%3}, {%4,%5,%6,%7}, {%8,%9}, {%0,%1,%2,%3};\n"
        : "+f"(d[0]), "+f"(d[1]), "+f"(d[2]), "+f"(d[3])
        : "r"(a[0]), "r"(a[1]), "r"(a[2]), "r"(a[3]), "r"(b[0]), "r"(b[1]));
}

// ---------------- tf32 tensor-core GEMM ----------------
// C[M,N] = A[M,K] @ B[K,N] (+bias). Row-major everywhere.
// Block = BM x BN x BK, 256 threads (8 warps), warp tile WM x WN,
// fragments m16n8k8. A smem m-major (conflict-free frag loads), B smem k-major.
template<int BM, int BN, int BK, int WM, int WN, bool BIAS>
__global__ __launch_bounds__(256)
void mma_gemm(int M, int N, int K,
              const float* __restrict__ A,
              const float* __restrict__ B,
              const float* __restrict__ bias,
              float* __restrict__ C) {
    constexpr int WARPS_N = BN / WN;
    constexpr int FM = WM / 16;
    constexpr int FN = WN / 8;
    constexpr int AV = BM * BK / (4 * 256);   // float4 chunks per thread (A)
    constexpr int BV = BK * BN / (4 * 256);   // float4 chunks per thread (B)
    constexpr int AC = BK / 4;                // float4 chunks per A row
    constexpr int BC = BN / 4;                // float4 chunks per B row

    __shared__ __align__(16) uint32_t As[BM][BK + 4];
    __shared__ __align__(16) uint32_t Bs[BK][BN + 4];

    const int tid  = threadIdx.x;
    const int wid  = tid >> 5;
    const int lane = tid & 31;
    const int g    = lane >> 2;
    const int tig  = lane & 3;
    const int wm   = (wid / WARPS_N) * WM;
    const int wn   = (wid % WARPS_N) * WN;
    const int bm0  = blockIdx.y * BM;
    const int bn0  = blockIdx.x * BN;

    float acc[FM][FN][4];
    #pragma unroll
    for (int i = 0; i < FM; i++)
        #pragma unroll
        for (int j = 0; j < FN; j++)
            #pragma unroll
            for (int r = 0; r < 4; r++) acc[i][j][r] = 0.f;

    float4 aR[AV], bR[BV];

    // prefetch stage 0
    #pragma unroll
    for (int i = 0; i < AV; i++) {
        int v = tid + i * 256;
        int r = v / AC, c4 = (v % AC) * 4;
        int gr = bm0 + r;
        aR[i] = (gr < M) ? *(const float4*)&A[(long)gr * K + c4]
                         : make_float4(0.f, 0.f, 0.f, 0.f);
    }
    #pragma unroll
    for (int i = 0; i < BV; i++) {
        int v = tid + i * 256;
        int r = v / BC, c4 = (v % BC) * 4;
        bR[i] = *(const float4*)&B[(long)r * N + bn0 + c4];
    }

    const int KT = K / BK;
    for (int kt = 0; kt < KT; kt++) {
        __syncthreads();
        // store staged tile to smem (convert to tf32)
        #pragma unroll
        for (int i = 0; i < AV; i++) {
            int v = tid + i * 256;
            int r = v / AC, c4 = (v % AC) * 4;
            uint4 u;
            u.x = f2tf32(aR[i].x); u.y = f2tf32(aR[i].y);
            u.z = f2tf32(aR[i].z); u.w = f2tf32(aR[i].w);
            *(uint4*)&As[r][c4] = u;
        }
        #pragma unroll
        for (int i = 0; i < BV; i++) {
            int v = tid + i * 256;
            int r = v / BC, c4 = (v % BC) * 4;
            uint4 u;
            u.x = f2tf32(bR[i].x); u.y = f2tf32(bR[i].y);
            u.z = f2tf32(bR[i].z); u.w = f2tf32(bR[i].w);
            *(uint4*)&Bs[r][c4] = u;
        }
        __syncthreads();

        // prefetch next stage
        if (kt + 1 < KT) {
            int k0 = (kt + 1) * BK;
            #pragma unroll
            for (int i = 0; i < AV; i++) {
                int v = tid + i * 256;
                int r = v / AC, c4 = (v % AC) * 4;
                int gr = bm0 + r;
                aR[i] = (gr < M) ? *(const float4*)&A[(long)gr * K + k0 + c4]
                                 : make_float4(0.f, 0.f, 0.f, 0.f);
            }
            #pragma unroll
            for (int i = 0; i < BV; i++) {
                int v = tid + i * 256;
                int r = v / BC, c4 = (v % BC) * 4;
                bR[i] = *(const float4*)&B[(long)(k0 + r) * N + bn0 + c4];
            }
        }

        // compute
        #pragma unroll
        for (int k8 = 0; k8 < BK; k8 += 8) {
            uint32_t af[FM][4], bf[FN][2];
            #pragma unroll
            for (int fm = 0; fm < FM; fm++) {
                int m = wm + fm * 16 + g;
                af[fm][0] = As[m    ][k8 + tig];
                af[fm][1] = As[m + 8][k8 + tig];
                af[fm][2] = As[m    ][k8 + tig + 4];
                af[fm][3] = As[m + 8][k8 + tig + 4];
            }
            #pragma unroll
            for (int fn = 0; fn < FN; fn++) {
                int n = wn + fn * 8 + g;
                bf[fn][0] = Bs[k8 + tig    ][n];
                bf[fn][1] = Bs[k8 + tig + 4][n];
            }
            #pragma unroll
            for (int fm = 0; fm < FM; fm++)
                #pragma unroll
                for (int fn = 0; fn < FN; fn++)
                    mma_tf32(acc[fm][fn], af[fm], bf[fn]);
        }
    }

    // epilogue
    #pragma unroll
    for (int fm = 0; fm < FM; fm++) {
        int r0 = bm0 + wm + fm * 16 + g;
        #pragma unroll
        for (int fn = 0; fn < FN; fn++) {
            int cb = bn0 + wn + fn * 8 + 2 * tig;
            float bx = 0.f, by = 0.f;
            if (BIAS) { bx = bias[cb]; by = bias[cb + 1]; }
            if (r0 < M) {
                float2 v = make_float2(acc[fm][fn][0] + bx, acc[fm][fn][1] + by);
                *(float2*)&C[(long)r0 * N + cb] = v;
            }
            if (r0 + 8 < M) {
                float2 v = make_float2(acc[fm][fn][2] + bx, acc[fm][fn][3] + by);
                *(float2*)&C[(long)(r0 + 8) * N + cb] = v;
            }
        }
    }
}

// ---------------- CSR construction ----------------
__global__ void csr_count(const int* __restrict__ dst, int* __restrict__ deg, int E) {
    int e = blockIdx.x * blockDim.x + threadIdx.x;
    if (e < E) atomicAdd(&deg[dst[e]], 1);
}

__global__ void csr_scan(const int* __restrict__ deg, int* __restrict__ rowptr) {
    __shared__ int part[1024];
    int tid = threadIdx.x;
    const int PER = (NN + 1023) / 1024;  // 10
    int base = tid * PER;
    int local[PER];
    int s = 0;
    #pragma unroll
    for (int i = 0; i < PER; i++) {
        int idx = base + i;
        local[i] = (idx < NN) ? deg[idx] : 0;
        s += local[i];
    }
    part[tid] = s;
    __syncthreads();
    for (int off = 1; off < 1024; off <<= 1) {
        int v = (tid >= off) ? part[tid - off] : 0;
        __syncthreads();
        part[tid] += v;
        __syncthreads();
    }
    int excl = part[tid] - s;
    #pragma unroll
    for (int i = 0; i < PER; i++) {
        int idx = base + i;
        if (idx < NN) rowptr[idx] = excl;
        excl += local[i];
    }
    if (tid == 1023) rowptr[NN] = excl;
}

__global__ void csr_fill(const int* __restrict__ dst, int* __restrict__ cursor,
                         int* __restrict__ eidx, int E) {
    int e = blockIdx.x * blockDim.x + threadIdx.x;
    if (e >= E) return;
    int p = atomicAdd(&cursor[dst[e]], 1);
    eidx[p] = e;
}

// ---------------- attention coefficients: el/er per (node, head) ----------------
__global__ void attn_coeff(const float* __restrict__ feat,
                           const float* __restrict__ al,
                           const float* __restrict__ ar,
                           float* __restrict__ el, float* __restrict__ er,
                           int n, int H, int D) {
    int idx = blockIdx.x * blockDim.x + threadIdx.x;
    if (idx >= n * H) return;
    int h = idx % H;
    float e1 = 0.f, e2 = 0.f;
    const float* f = feat + (long)idx * D;
    const float* wl = al + h * D;
    const float* wr = ar + h * D;
    #pragma unroll 8
    for (int d = 0; d < D; d++) {
        float v = f[d];
        e1 += v * wl[d];
        e2 += v * wr[d];
    }
    el[idx] = e1;
    er[idx] = e2;
}

__device__ __forceinline__ float leaky(float x) { return (x >= 0.f) ? x : 0.2f * x; }

// ---------------- per-edge leaky-relu logits, layer 1 (8 heads) ----------------
__global__ void edge_logits1(const int* __restrict__ src, const int* __restrict__ dst,
                             const float* __restrict__ el, const float* __restrict__ er,
                             float* __restrict__ out, int E) {
    int e = blockIdx.x * blockDim.x + threadIdx.x;
    if (e >= E) return;
    const float4* lp = (const float4*)(el + (long)src[e]*8);
    const float4* rp = (const float4*)(er + (long)dst[e]*8);
    float4 l0 = lp[0], l1 = lp[1];
    float4 r0 = rp[0], r1 = rp[1];
    float4 o0, o1;
    o0.x = leaky(l0.x + r0.x); o0.y = leaky(l0.y + r0.y);
    o0.z = leaky(l0.z + r0.z); o0.w = leaky(l0.w + r0.w);
    o1.x = leaky(l1.x + r1.x); o1.y = leaky(l1.y + r1.y);
    o1.z = leaky(l1.z + r1.z); o1.w = leaky(l1.w + r1.w);
    float4* op = (float4*)(out + (long)e*8);
    op[0] = o0; op[1] = o1;
}

// ---------------- per-edge logits, layer 2 (1 head) ----------------
__global__ void edge_logits2(const int* __restrict__ src, const int* __restrict__ dst,
                             const float* __restrict__ el, const float* __restrict__ er,
                             float* __restrict__ out, int E) {
    int e = blockIdx.x * blockDim.x + threadIdx.x;
    if (e >= E) return;
    out[e] = leaky(el[src[e]] + er[dst[e]]);
}

// ---------------- gather aggregation, layer 1: warp per node, 8 heads ----------------
__global__ void gat_gather1(const int* __restrict__ rowptr, const int* __restrict__ eidx,
                            const int* __restrict__ src,
                            const float* __restrict__ logits,   // [E,8]
                            const float* __restrict__ feat,     // [N,256]
                            float* __restrict__ rst) {
    int node = blockIdx.x * (blockDim.x >> 5) + (threadIdx.x >> 5);
    int lane = threadIdx.x & 31;
    if (node >= NN) return;
    int s0 = rowptr[node], deg = rowptr[node+1] - s0;

    // pass 1: per-head max
    float m[8];
    #pragma unroll
    for (int h = 0; h < 8; h++) m[h] = -3.4e38f;
    for (int i = lane; i < deg; i += 32) {
        int e = eidx[s0 + i];
        const float4* lp = (const float4*)(logits + (long)e*8);
        float4 a = lp[0], b = lp[1];
        m[0]=fmaxf(m[0],a.x); m[1]=fmaxf(m[1],a.y); m[2]=fmaxf(m[2],a.z); m[3]=fmaxf(m[3],a.w);
        m[4]=fmaxf(m[4],b.x); m[5]=fmaxf(m[5],b.y); m[6]=fmaxf(m[6],b.z); m[7]=fmaxf(m[7],b.w);
    }
    #pragma unroll
    for (int h = 0; h < 8; h++)
        #pragma unroll
        for (int off = 16; off; off >>= 1)
            m[h] = fmaxf(m[h], __shfl_xor_sync(0xffffffffu, m[h], off));

    // pass 2: exp-sum
    float s[8];
    #pragma unroll
    for (int h = 0; h < 8; h++) s[h] = 0.f;
    for (int i = lane; i < deg; i += 32) {
        int e = eidx[s0 + i];
        const float4* lp = (const float4*)(logits + (long)e*8);
        float4 a = lp[0], b = lp[1];
        s[0]+=expf(a.x-m[0]); s[1]+=expf(a.y-m[1]); s[2]+=expf(a.z-m[2]); s[3]+=expf(a.w-m[3]);
        s[4]+=expf(b.x-m[4]); s[5]+=expf(b.y-m[5]); s[6]+=expf(b.z-m[6]); s[7]+=expf(b.w-m[7]);
    }
    #pragma unroll
    for (int h = 0; h < 8; h++) {
        #pragma unroll
        for (int off = 16; off; off >>= 1)
            s[h] += __shfl_xor_sync(0xffffffffu, s[h], off);
        s[h] = 1.f / (s[h] + 1e-16f);
    }

    // pass 3: weighted aggregation (lane = channel within each head)
    float acc[8];
    #pragma unroll
    for (int h = 0; h < 8; h++) acc[h] = 0.f;
    for (int base = 0; base < deg; base += 32) {
        int cnt = min(32, deg - base);
        float al[8]; int sv = 0;
        #pragma unroll
        for (int h = 0; h < 8; h++) al[h] = 0.f;
        if (lane < cnt) {
            int e = eidx[s0 + base + lane];
            sv = src[e];
            const float4* lp = (const float4*)(logits + (long)e*8);
            float4 a = lp[0], b = lp[1];
            al[0]=expf(a.x-m[0])*s[0]; al[1]=expf(a.y-m[1])*s[1];
            al[2]=expf(a.z-m[2])*s[2]; al[3]=expf(a.w-m[3])*s[3];
            al[4]=expf(b.x-m[4])*s[4]; al[5]=expf(b.y-m[5])*s[5];
            al[6]=expf(b.z-m[6])*s[6]; al[7]=expf(b.w-m[7])*s[7];
        }
        for (int j = 0; j < cnt; j++) {
            int sn = __shfl_sync(0xffffffffu, sv, j);
            const float* fp = feat + (long)sn*HDIM + lane;
            #pragma unroll
            for (int h = 0; h < 8; h++) {
                float a = __shfl_sync(0xffffffffu, al[h], j);
                acc[h] = fmaf(a, fp[h*32], acc[h]);
            }
        }
    }
    float* rp = rst + (long)node*HDIM + lane;
    #pragma unroll
    for (int h = 0; h < 8; h++) rp[h*32] = acc[h];
}

// ---------------- gather aggregation, layer 2: warp per node, 1 head ----------------
__global__ void gat_gather2(const int* __restrict__ rowptr, const int* __restrict__ eidx,
                            const int* __restrict__ src,
                            const float* __restrict__ logits,   // [E]
                            const float* __restrict__ feat,     // [N,32]
                            float* __restrict__ rst) {
    int node = blockIdx.x * (blockDim.x >> 5) + (threadIdx.x >> 5);
    int lane = threadIdx.x & 31;
    if (node >= NN) return;
    int s0 = rowptr[node], deg = rowptr[node+1] - s0;

    float m = -3.4e38f;
    for (int i = lane; i < deg; i += 32)
        m = fmaxf(m, logits[eidx[s0 + i]]);
    #pragma unroll
    for (int off = 16; off; off >>= 1)
        m = fmaxf(m, __shfl_xor_sync(0xffffffffu, m, off));

    float s = 0.f;
    for (int i = lane; i < deg; i += 32)
        s += expf(logits[eidx[s0 + i]] - m);
    #pragma unroll
    for (int off = 16; off; off >>= 1)
        s += __shfl_xor_sync(0xffffffffu, s, off);
    float inv = 1.f / (s + 1e-16f);

    float acc = 0.f;
    for (int base = 0; base < deg; base += 32) {
        int cnt = min(32, deg - base);
        float al = 0.f; int sv = 0;
        if (lane < cnt) {
            int e = eidx[s0 + base + lane];
            sv = src[e];
            al = expf(logits[e] - m) * inv;
        }
        for (int j = 0; j < cnt; j++) {
            int sn = __shfl_sync(0xffffffffu, sv, j);
            float a = __shfl_sync(0xffffffffu, al, j);
            acc = fmaf(a, feat[(long)sn*D2 + lane], acc);
        }
    }
    rst[(long)node*D2 + lane] = acc;
}

// ---------------- BN batch stats: per-channel sum & sumsq ----------------
__global__ void bn_stats(const float* __restrict__ x,
                         float* __restrict__ gsum, float* __restrict__ gsq,
                         int n, int C) {
    int tid = threadIdx.x;
    int c  = tid % C;
    int rl = tid / C;
    int L  = blockDim.x / C;
    int rows = (n + gridDim.x - 1) / gridDim.x;
    int r0 = blockIdx.x * rows;
    int r1 = min(n, r0 + rows);
    float s = 0.f, q = 0.f;
    for (int r = r0 + rl; r < r1; r += L) {
        float v = x[(long)r*C + c];
        s += v; q += v*v;
    }
    __shared__ float ss[256], sq[256];
    ss[tid] = s; sq[tid] = q;
    __syncthreads();
    if (rl == 0) {
        for (int l = 1; l < L; l++) { s += ss[l*C + c]; q += sq[l*C + c]; }
        atomicAdd(&gsum[c], s);
        atomicAdd(&gsq[c],  q);
    }
}

// ---------------- BN apply + ELU (+ optional residual) ----------------
__global__ void bn_apply(const float* __restrict__ x,
                         const float* __restrict__ gsum, const float* __restrict__ gsq,
                         const float* __restrict__ g, const float* __restrict__ b,
                         const float* __restrict__ resid,
                         float* __restrict__ out, int n, int C) {
    int idx = blockIdx.x * blockDim.x + threadIdx.x;
    if (idx >= n * C) return;
    int c = idx % C;
    float inv_n = 1.f / (float)n;
    float mu  = gsum[c] * inv_n;
    float var = gsq[c] * inv_n - mu*mu;
    float y = g[c] * (x[idx] - mu) * rsqrtf(var + 1e-5f) + b[c];
    y = (y > 0.f) ? y : expm1f(y);
    if (resid) y += resid[idx];
    out[idx] = y;
}

// ---------------- host launch ----------------
static inline void* sym(const void* s) {
    void* p = nullptr;
    cudaGetSymbolAddress(&p, s);
    return p;
}

extern "C" void kernel_launch(void* const* d_in, const int* in_sizes, int n_in,
                              void* d_out, int out_size) {
    const float* h     = (const float*)d_in[0];
    const int*   src   = (const int*)  d_in[2];
    const int*   dst   = (const int*)  d_in[3];
    const float* W_emb = (const float*)d_in[4];
    const float* b_emb = (const float*)d_in[5];
    const float* fc1   = (const float*)d_in[18];
    const float* al1   = (const float*)d_in[19];
    const float* ar1   = (const float*)d_in[20];
    const float* g1    = (const float*)d_in[21];
    const float* b1    = (const float*)d_in[22];
    const float* fc2   = (const float*)d_in[23];
    const float* al2   = (const float*)d_in[24];
    const float* ar2   = (const float*)d_in[25];
    const float* g2    = (const float*)d_in[26];
    const float* b2    = (const float*)d_in[27];
    float* out = (float*)d_out;

    float* hh0   = (float*)sym(g_hh0);
    float* feat1 = (float*)sym(g_feat1);
    float* rst1  = (float*)sym(g_rst1);
    float* hh1   = (float*)sym(g_hh1);
    float* el1   = (float*)sym(g_el1);
    float* er1   = (float*)sym(g_er1);
    float* feat2 = (float*)sym(g_feat2);
    float* rst2  = (float*)sym(g_rst2);
    float* el2   = (float*)sym(g_el2);
    float* er2   = (float*)sym(g_er2);
    float* bnsum1= (float*)sym(g_bnsum1);
    float* bnsq1 = (float*)sym(g_bnsq1);
    float* bnsum2= (float*)sym(g_bnsum2);
    float* bnsq2 = (float*)sym(g_bnsq2);
    int*   deg   = (int*)  sym(g_deg);
    int*   rowptr= (int*)  sym(g_rowptr);
    int*   cursor= (int*)  sym(g_cursor);
    int*   eidx  = (int*)  sym(g_eidx);
    float* log1  = (float*)sym(g_logits1);
    float* log2  = (float*)sym(g_logits2);

    // zero accumulators (graph replays must be deterministic)
    cudaMemsetAsync(deg,   0, sizeof(int)*NN);
    cudaMemsetAsync(bnsum1,0, sizeof(float)*HDIM);
    cudaMemsetAsync(bnsq1, 0, sizeof(float)*HDIM);
    cudaMemsetAsync(bnsum2,0, sizeof(float)*D2);
    cudaMemsetAsync(bnsq2, 0, sizeof(float)*D2);

    // CSR by destination
    csr_count<<<(NE + 255)/256, 256>>>(dst, deg, NE);
    csr_scan <<<1, 1024>>>(deg, rowptr);
    cudaMemcpyAsync(cursor, rowptr, sizeof(int)*NN, cudaMemcpyDeviceToDevice);
    csr_fill <<<(NE + 255)/256, 256>>>(dst, cursor, eidx, NE);

    // 1) hh0 = h @ W_emb + b_emb    [10000,128]x[128,256]
    {
        dim3 grid(HDIM/128, (NN + 63)/64);
        mma_gemm<64,128,32,32,32,true><<<grid, 256>>>(NN, HDIM, IND, h, W_emb, b_emb, hh0);
    }
    // 2) feat1 = hh0 @ fc1          [10000,256]x[256,256]
    {
        dim3 grid(HDIM/128, (NN + 63)/64);
        mma_gemm<64,128,32,32,32,false><<<grid, 256>>>(NN, HDIM, HDIM, hh0, fc1, nullptr, feat1);
    }
    // 3) el/er, per-edge logits
    attn_coeff <<<(NN*H1 + 255)/256, 256>>>(feat1, al1, ar1, el1, er1, NN, H1, D1);
    edge_logits1<<<(NE + 255)/256, 256>>>(src, dst, el1, er1, log1, NE);
    // 4) gather aggregation (no atomics)
    gat_gather1<<<(NN*32 + 255)/256, 256>>>(rowptr, eidx, src, log1, feat1, rst1);
    // 5) BN + ELU + residual -> hh1
    bn_stats<<<157, 256>>>(rst1, bnsum1, bnsq1, NN, HDIM);
    bn_apply<<<(NN*HDIM + 255)/256, 256>>>(rst1, bnsum1, bnsq1, g1, b1, hh0, hh1, NN, HDIM);

    // 6) feat2 = hh1 @ fc2          [10000,256]x[256,32]
    {
        dim3 grid(1, (NN + 63)/64);
        mma_gemm<64,32,32,16,16,false><<<grid, 256>>>(NN, D2, HDIM, hh1, fc2, nullptr, feat2);
    }
    // 7) layer-2 attention
    attn_coeff <<<(NN + 255)/256, 256>>>(feat2, al2, ar2, el2, er2, NN, H2, D2);
    edge_logits2<<<(NE + 255)/256, 256>>>(src, dst, el2, er2, log2, NE);
    gat_gather2<<<(NN*32 + 255)/256, 256>>>(rowptr, eidx, src, log2, feat2, rst2);
    // 8) BN + ELU -> out
    bn_stats<<<157, 256>>>(rst2, bnsum2, bnsq2, NN, D2);
    bn_apply<<<(NN*D2 + 255)/256, 256>>>(rst2, bnsum2, bnsq2, g2, b2, nullptr, out, NN, D2);

    (void)in_sizes; (void)n_in; (void)out_size;
}

// round 7
// speedup vs baseline: 3.5360x; 1.0692x over previous
#include <cuda_runtime.h>
#include <math.h>
#include <stdint.h>

#define NN    10000
#define NE    120000
#define IND   128
#define HDIM  256
#define H1    8
#define H2    1
#define D2    32

// ---------------- scratch (device globals; no allocations) ----------------
__device__ float    g_hh0  [NN*HDIM];
__device__ float    g_feat1[NN*HDIM];
__device__ float    g_rst1 [NN*HDIM];
__device__ float    g_el1  [NN*H1];
__device__ float    g_er1  [NN*H1];
__device__ float    g_feat2[NN*D2];
__device__ float    g_rst2 [NN*D2];
__device__ float    g_el2  [NN];
__device__ float    g_er2  [NN];
// BN accumulators packed: [sum1(256) | sq1(256) | sum2(32) | sq2(32)]
__device__ float    g_bnacc[2*HDIM + 2*D2];
__device__ float    g_bns1 [HDIM];   // per-channel scale
__device__ float    g_bnt1 [HDIM];   // per-channel shift
// CSR by destination
__device__ int      g_deg   [NN];
__device__ int      g_rowptr[NN+1];
__device__ int      g_cursor[NN];
__device__ int      g_eidx  [NE];

// ---------------- tf32 helpers ----------------
__device__ __forceinline__ uint32_t f2tf32(float f) {
    uint32_t u;
    asm("cvt.rna.tf32.f32 %0, %1;" : "=r"(u) : "f"(f));
    return u;
}

__device__ __forceinline__ void mma_tf32(float* d, const uint32_t* a, const uint32_t* b) {
    asm volatile(
        "mma.sync.aligned.m16n8k8.row.col.f32.tf32.tf32.f32 "
        "{%0,%1,%2,%3}, {%4,%5,%6,%7}, {%8,%9}, {%0,%1,%2,%3};\n"
        : "+f"(d[0]), "+f"(d[1]), "+f"(d[2]), "+f"(d[3])
        : "r"(a[0]), "r"(a[1]), "r"(a[2]), "r"(a[3]), "r"(b[0]), "r"(b[1]));
}

__device__ __forceinline__ float elu1(float y) { return (y > 0.f) ? y : expm1f(y); }

// ---------------- tf32 tensor-core GEMM ----------------
// C[M,N] = A'[M,K] @ B[K,N] (+bias).
// FUSE_BN: A'[i,c] = HH0[i,c] + elu(A[i,c]*bns[c] + bnt[c])   (layer-1 BN+ELU+residual)
template<int BM, int BN, int BK, int WM, int WN, bool BIAS, bool FUSE_BN>
__global__ __launch_bounds__(256)
void mma_gemm(int M, int N, int K,
              const float* __restrict__ A,
              const float* __restrict__ B,
              const float* __restrict__ bias,
              const float* __restrict__ HH0,
              const float* __restrict__ bns,
              const float* __restrict__ bnt,
              float* __restrict__ C) {
    constexpr int WARPS_N = BN / WN;
    constexpr int FM = WM / 16;
    constexpr int FN = WN / 8;
    constexpr int AV = BM * BK / (4 * 256);
    constexpr int BV = BK * BN / (4 * 256);
    constexpr int AC = BK / 4;
    constexpr int BC = BN / 4;

    __shared__ __align__(16) uint32_t As[BM][BK + 4];
    __shared__ __align__(16) uint32_t Bs[BK][BN + 4];

    const int tid  = threadIdx.x;
    const int wid  = tid >> 5;
    const int lane = tid & 31;
    const int g    = lane >> 2;
    const int tig  = lane & 3;
    const int wm   = (wid / WARPS_N) * WM;
    const int wn   = (wid % WARPS_N) * WN;
    const int bm0  = blockIdx.y * BM;
    const int bn0  = blockIdx.x * BN;

    float acc[FM][FN][4];
    #pragma unroll
    for (int i = 0; i < FM; i++)
        #pragma unroll
        for (int j = 0; j < FN; j++)
            #pragma unroll
            for (int r = 0; r < 4; r++) acc[i][j][r] = 0.f;

    float4 aR[AV], bR[BV];

    auto loadA = [&](int k0) {
        #pragma unroll
        for (int i = 0; i < AV; i++) {
            int v = tid + i * 256;
            int r = v / AC, c4 = (v % AC) * 4;
            int gr = bm0 + r;
            float4 x = make_float4(0.f, 0.f, 0.f, 0.f);
            if (gr < M) {
                x = *(const float4*)&A[(long)gr * K + k0 + c4];
                if (FUSE_BN) {
                    int c = k0 + c4;
                    float4 hv = *(const float4*)&HH0[(long)gr * K + c];
                    x.x = hv.x + elu1(x.x * bns[c    ] + bnt[c    ]);
                    x.y = hv.y + elu1(x.y * bns[c + 1] + bnt[c + 1]);
                    x.z = hv.z + elu1(x.z * bns[c + 2] + bnt[c + 2]);
                    x.w = hv.w + elu1(x.w * bns[c + 3] + bnt[c + 3]);
                }
            }
            aR[i] = x;
        }
    };
    auto loadB = [&](int k0) {
        #pragma unroll
        for (int i = 0; i < BV; i++) {
            int v = tid + i * 256;
            int r = v / BC, c4 = (v % BC) * 4;
            bR[i] = *(const float4*)&B[(long)(k0 + r) * N + bn0 + c4];
        }
    };

    loadA(0);
    loadB(0);

    const int KT = K / BK;
    for (int kt = 0; kt < KT; kt++) {
        __syncthreads();
        #pragma unroll
        for (int i = 0; i < AV; i++) {
            int v = tid + i * 256;
            int r = v / AC, c4 = (v % AC) * 4;
            uint4 u;
            u.x = f2tf32(aR[i].x); u.y = f2tf32(aR[i].y);
            u.z = f2tf32(aR[i].z); u.w = f2tf32(aR[i].w);
            *(uint4*)&As[r][c4] = u;
        }
        #pragma unroll
        for (int i = 0; i < BV; i++) {
            int v = tid + i * 256;
            int r = v / BC, c4 = (v % BC) * 4;
            uint4 u;
            u.x = f2tf32(bR[i].x); u.y = f2tf32(bR[i].y);
            u.z = f2tf32(bR[i].z); u.w = f2tf32(bR[i].w);
            *(uint4*)&Bs[r][c4] = u;
        }
        __syncthreads();

        if (kt + 1 < KT) {
            loadA((kt + 1) * BK);
            loadB((kt + 1) * BK);
        }

        #pragma unroll
        for (int k8 = 0; k8 < BK; k8 += 8) {
            uint32_t af[FM][4], bf[FN][2];
            #pragma unroll
            for (int fm = 0; fm < FM; fm++) {
                int m = wm + fm * 16 + g;
                af[fm][0] = As[m    ][k8 + tig];
                af[fm][1] = As[m + 8][k8 + tig];
                af[fm][2] = As[m    ][k8 + tig + 4];
                af[fm][3] = As[m + 8][k8 + tig + 4];
            }
            #pragma unroll
            for (int fn = 0; fn < FN; fn++) {
                int n = wn + fn * 8 + g;
                bf[fn][0] = Bs[k8 + tig    ][n];
                bf[fn][1] = Bs[k8 + tig + 4][n];
            }
            #pragma unroll
            for (int fm = 0; fm < FM; fm++)
                #pragma unroll
                for (int fn = 0; fn < FN; fn++)
                    mma_tf32(acc[fm][fn], af[fm], bf[fn]);
        }
    }

    #pragma unroll
    for (int fm = 0; fm < FM; fm++) {
        int r0 = bm0 + wm + fm * 16 + g;
        #pragma unroll
        for (int fn = 0; fn < FN; fn++) {
            int cb = bn0 + wn + fn * 8 + 2 * tig;
            float bx = 0.f, by = 0.f;
            if (BIAS) { bx = bias[cb]; by = bias[cb + 1]; }
            if (r0 < M) {
                float2 v = make_float2(acc[fm][fn][0] + bx, acc[fm][fn][1] + by);
                *(float2*)&C[(long)r0 * N + cb] = v;
            }
            if (r0 + 8 < M) {
                float2 v = make_float2(acc[fm][fn][2] + bx, acc[fm][fn][3] + by);
                *(float2*)&C[(long)(r0 + 8) * N + cb] = v;
            }
        }
    }
}

// ---------------- CSR construction ----------------
__global__ void csr_count(const int* __restrict__ dst, int* __restrict__ deg, int E) {
    int e = blockIdx.x * blockDim.x + threadIdx.x;
    if (e < E) atomicAdd(&deg[dst[e]], 1);
}

__global__ void csr_scan(const int* __restrict__ deg, int* __restrict__ rowptr,
                         int* __restrict__ cursor) {
    __shared__ int part[1024];
    int tid = threadIdx.x;
    const int PER = (NN + 1023) / 1024;  // 10
    int base = tid * PER;
    int local[PER];
    int s = 0;
    #pragma unroll
    for (int i = 0; i < PER; i++) {
        int idx = base + i;
        local[i] = (idx < NN) ? deg[idx] : 0;
        s += local[i];
    }
    part[tid] = s;
    __syncthreads();
    for (int off = 1; off < 1024; off <<= 1) {
        int v = (tid >= off) ? part[tid - off] : 0;
        __syncthreads();
        part[tid] += v;
        __syncthreads();
    }
    int excl = part[tid] - s;
    #pragma unroll
    for (int i = 0; i < PER; i++) {
        int idx = base + i;
        if (idx < NN) { rowptr[idx] = excl; cursor[idx] = excl; }
        excl += local[i];
    }
    if (tid == 1023) rowptr[NN] = excl;
}

__global__ void csr_fill(const int* __restrict__ dst, int* __restrict__ cursor,
                         int* __restrict__ eidx, int E) {
    int e = blockIdx.x * blockDim.x + threadIdx.x;
    if (e >= E) return;
    int p = atomicAdd(&cursor[dst[e]], 1);
    eidx[p] = e;
}

// ---------------- attention coefficients: el/er per (node, head) ----------------
__global__ void attn_coeff(const float* __restrict__ feat,
                           const float* __restrict__ al,
                           const float* __restrict__ ar,
                           float* __restrict__ el, float* __restrict__ er,
                           int n, int H, int D) {
    int idx = blockIdx.x * blockDim.x + threadIdx.x;
    if (idx >= n * H) return;
    int h = idx % H;
    float e1 = 0.f, e2 = 0.f;
    const float* f = feat + (long)idx * D;
    const float* wl = al + h * D;
    const float* wr = ar + h * D;
    #pragma unroll 8
    for (int d = 0; d < D; d++) {
        float v = f[d];
        e1 += v * wl[d];
        e2 += v * wr[d];
    }
    el[idx] = e1;
    er[idx] = e2;
}

__device__ __forceinline__ float leaky(float x) { return (x >= 0.f) ? x : 0.2f * x; }

// ---------------- gather aggregation, layer 1 ----------------
// warp per node, 8 heads, single-pass online softmax, logits computed inline
__global__ void gat_gather1(const int* __restrict__ rowptr, const int* __restrict__ eidx,
                            const int* __restrict__ src,
                            const float* __restrict__ el,    // [N,8]
                            const float* __restrict__ er,    // [N,8]
                            const float* __restrict__ feat,  // [N,256]
                            float* __restrict__ rst) {
    int node = blockIdx.x * (blockDim.x >> 5) + (threadIdx.x >> 5);
    int lane = threadIdx.x & 31;
    if (node >= NN) return;
    int s0 = rowptr[node], deg = rowptr[node+1] - s0;

    // er for this node is warp-uniform
    const float4* erp = (const float4*)(er + (long)node*8);
    float4 er0 = erp[0], er1v = erp[1];
    float erh[8] = {er0.x, er0.y, er0.z, er0.w, er1v.x, er1v.y, er1v.z, er1v.w};

    float m[8], s[8], acc[8];
    #pragma unroll
    for (int h = 0; h < 8; h++) { m[h] = -3.0e38f; s[h] = 0.f; acc[h] = 0.f; }

    for (int base = 0; base < deg; base += 32) {
        int cnt = min(32, deg - base);
        int sv = 0;
        float l[8];
        #pragma unroll
        for (int h = 0; h < 8; h++) l[h] = -3.0e38f;
        if (lane < cnt) {
            int e = eidx[s0 + base + lane];
            sv = src[e];
            const float4* lp = (const float4*)(el + (long)sv*8);
            float4 a = lp[0], b = lp[1];
            l[0] = leaky(a.x + erh[0]); l[1] = leaky(a.y + erh[1]);
            l[2] = leaky(a.z + erh[2]); l[3] = leaky(a.w + erh[3]);
            l[4] = leaky(b.x + erh[4]); l[5] = leaky(b.y + erh[5]);
            l[6] = leaky(b.z + erh[6]); l[7] = leaky(b.w + erh[7]);
        }
        float p[8];
        #pragma unroll
        for (int h = 0; h < 8; h++) {
            float cm = l[h];
            #pragma unroll
            for (int off = 16; off; off >>= 1)
                cm = fmaxf(cm, __shfl_xor_sync(0xffffffffu, cm, off));
            float nm = fmaxf(m[h], cm);
            float r = __expf(m[h] - nm);      // 0 on first chunk, 1 if max unchanged
            s[h]  *= r;
            acc[h] *= r;
            p[h] = __expf(l[h] - nm);          // 0 for inactive lanes (l = -3e38)
            float ps = p[h];
            #pragma unroll
            for (int off = 16; off; off >>= 1)
                ps += __shfl_xor_sync(0xffffffffu, ps, off);
            s[h] += ps;
            m[h] = nm;
        }
        for (int j = 0; j < cnt; j++) {
            int sn = __shfl_sync(0xffffffffu, sv, j);
            const float* fp = feat + (long)sn*HDIM + lane;
            #pragma unroll
            for (int h = 0; h < 8; h++) {
                float a = __shfl_sync(0xffffffffu, p[h], j);
                acc[h] = fmaf(a, fp[h*32], acc[h]);
            }
        }
    }
    float* rp = rst + (long)node*HDIM + lane;
    #pragma unroll
    for (int h = 0; h < 8; h++) rp[h*32] = acc[h] / (s[h] + 1e-16f);
}

// ---------------- gather aggregation, layer 2 (1 head) ----------------
__global__ void gat_gather2(const int* __restrict__ rowptr, const int* __restrict__ eidx,
                            const int* __restrict__ src,
                            const float* __restrict__ el,    // [N]
                            const float* __restrict__ er,    // [N]
                            const float* __restrict__ feat,  // [N,32]
                            float* __restrict__ rst) {
    int node = blockIdx.x * (blockDim.x >> 5) + (threadIdx.x >> 5);
    int lane = threadIdx.x & 31;
    if (node >= NN) return;
    int s0 = rowptr[node], deg = rowptr[node+1] - s0;
    float ern = er[node];

    float m = -3.0e38f, s = 0.f, acc = 0.f;
    for (int base = 0; base < deg; base += 32) {
        int cnt = min(32, deg - base);
        int sv = 0;
        float l = -3.0e38f;
        if (lane < cnt) {
            int e = eidx[s0 + base + lane];
            sv = src[e];
            l = leaky(el[sv] + ern);
        }
        float cm = l;
        #pragma unroll
        for (int off = 16; off; off >>= 1)
            cm = fmaxf(cm, __shfl_xor_sync(0xffffffffu, cm, off));
        float nm = fmaxf(m, cm);
        float r = __expf(m - nm);
        s *= r; acc *= r;
        float p = __expf(l - nm);
        float ps = p;
        #pragma unroll
        for (int off = 16; off; off >>= 1)
            ps += __shfl_xor_sync(0xffffffffu, ps, off);
        s += ps;
        m = nm;
        for (int j = 0; j < cnt; j++) {
            int sn = __shfl_sync(0xffffffffu, sv, j);
            float a = __shfl_sync(0xffffffffu, p, j);
            acc = fmaf(a, feat[(long)sn*D2 + lane], acc);
        }
    }
    rst[(long)node*D2 + lane] = acc / (s + 1e-16f);
}

// ---------------- BN batch stats: per-channel sum & sumsq ----------------
__global__ void bn_stats(const float* __restrict__ x,
                         float* __restrict__ gsum, float* __restrict__ gsq,
                         int n, int C) {
    int tid = threadIdx.x;
    int c  = tid % C;
    int rl = tid / C;
    int L  = blockDim.x / C;
    int rows = (n + gridDim.x - 1) / gridDim.x;
    int r0 = blockIdx.x * rows;
    int r1 = min(n, r0 + rows);
    float s = 0.f, q = 0.f;
    for (int r = r0 + rl; r < r1; r += L) {
        float v = x[(long)r*C + c];
        s += v; q += v*v;
    }
    __shared__ float ss[256], sq[256];
    ss[tid] = s; sq[tid] = q;
    __syncthreads();
    if (rl == 0) {
        for (int l = 1; l < L; l++) { s += ss[l*C + c]; q += sq[l*C + c]; }
        atomicAdd(&gsum[c], s);
        atomicAdd(&gsq[c],  q);
    }
}

// ---------------- BN finalize: (sum,sq,g,b) -> per-channel (scale,shift) ----------------
__global__ void bn_finalize(const float* __restrict__ gsum, const float* __restrict__ gsq,
                            const float* __restrict__ g, const float* __restrict__ b,
                            float* __restrict__ sc, float* __restrict__ sh, int n, int C) {
    int c = blockIdx.x * blockDim.x + threadIdx.x;
    if (c >= C) return;
    float inv_n = 1.f / (float)n;
    float mu  = gsum[c] * inv_n;
    float var = gsq[c] * inv_n - mu*mu;
    float rstd = rsqrtf(var + 1e-5f);
    float s = g[c] * rstd;
    sc[c] = s;
    sh[c] = b[c] - mu * s;
}

// ---------------- BN apply + ELU (layer 2 -> output) ----------------
__global__ void bn_apply(const float* __restrict__ x,
                         const float* __restrict__ gsum, const float* __restrict__ gsq,
                         const float* __restrict__ g, const float* __restrict__ b,
                         float* __restrict__ out, int n, int C) {
    int idx = blockIdx.x * blockDim.x + threadIdx.x;
    if (idx >= n * C) return;
    int c = idx % C;
    float inv_n = 1.f / (float)n;
    float mu  = gsum[c] * inv_n;
    float var = gsq[c] * inv_n - mu*mu;
    float y = g[c] * (x[idx] - mu) * rsqrtf(var + 1e-5f) + b[c];
    out[idx] = elu1(y);
}

// ---------------- host launch ----------------
static inline void* sym(const void* s) {
    void* p = nullptr;
    cudaGetSymbolAddress(&p, s);
    return p;
}

extern "C" void kernel_launch(void* const* d_in, const int* in_sizes, int n_in,
                              void* d_out, int out_size) {
    const float* h     = (const float*)d_in[0];
    const int*   src   = (const int*)  d_in[2];
    const int*   dst   = (const int*)  d_in[3];
    const float* W_emb = (const float*)d_in[4];
    const float* b_emb = (const float*)d_in[5];
    const float* fc1   = (const float*)d_in[18];
    const float* al1   = (const float*)d_in[19];
    const float* ar1   = (const float*)d_in[20];
    const float* g1    = (const float*)d_in[21];
    const float* b1    = (const float*)d_in[22];
    const float* fc2   = (const float*)d_in[23];
    const float* al2   = (const float*)d_in[24];
    const float* ar2   = (const float*)d_in[25];
    const float* g2    = (const float*)d_in[26];
    const float* b2    = (const float*)d_in[27];
    float* out = (float*)d_out;

    float* hh0   = (float*)sym(g_hh0);
    float* feat1 = (float*)sym(g_feat1);
    float* rst1  = (float*)sym(g_rst1);
    float* el1   = (float*)sym(g_el1);
    float* er1   = (float*)sym(g_er1);
    float* feat2 = (float*)sym(g_feat2);
    float* rst2  = (float*)sym(g_rst2);
    float* el2   = (float*)sym(g_el2);
    float* er2   = (float*)sym(g_er2);
    float* bnacc = (float*)sym(g_bnacc);
    float* bns1  = (float*)sym(g_bns1);
    float* bnt1  = (float*)sym(g_bnt1);
    int*   deg   = (int*)  sym(g_deg);
    int*   rowptr= (int*)  sym(g_rowptr);
    int*   cursor= (int*)  sym(g_cursor);
    int*   eidx  = (int*)  sym(g_eidx);

    float* bnsum1 = bnacc;
    float* bnsq1  = bnacc + HDIM;
    float* bnsum2 = bnacc + 2*HDIM;
    float* bnsq2  = bnacc + 2*HDIM + D2;

    // zero accumulators (graph replays must be deterministic)
    cudaMemsetAsync(deg,   0, sizeof(int)*NN);
    cudaMemsetAsync(bnacc, 0, sizeof(float)*(2*HDIM + 2*D2));

    // CSR by destination (scan also seeds cursor)
    csr_count<<<(NE + 255)/256, 256>>>(dst, deg, NE);
    csr_scan <<<1, 1024>>>(deg, rowptr, cursor);
    csr_fill <<<(NE + 255)/256, 256>>>(dst, cursor, eidx, NE);

    // 1) hh0 = h @ W_emb + b_emb    [10000,128]x[128,256]
    {
        dim3 grid(HDIM/128, (NN + 63)/64);
        mma_gemm<64,128,32,32,32,true,false><<<grid, 256>>>(
            NN, HDIM, IND, h, W_emb, b_emb, nullptr, nullptr, nullptr, hh0);
    }
    // 2) feat1 = hh0 @ fc1          [10000,256]x[256,256]
    {
        dim3 grid(HDIM/128, (NN + 63)/64);
        mma_gemm<64,128,32,32,32,false,false><<<grid, 256>>>(
            NN, HDIM, HDIM, hh0, fc1, nullptr, nullptr, nullptr, nullptr, feat1);
    }
    // 3) attention coefficients + fused-logit gather (single pass, online softmax)
    attn_coeff <<<(NN*H1 + 255)/256, 256>>>(feat1, al1, ar1, el1, er1, NN, H1, D2);
    gat_gather1<<<(NN*32 + 255)/256, 256>>>(rowptr, eidx, src, el1, er1, feat1, rst1);
    // 4) BN stats + finalize (apply is fused into the next GEMM's A-load)
    bn_stats   <<<157, 256>>>(rst1, bnsum1, bnsq1, NN, HDIM);
    bn_finalize<<<1, HDIM>>>(bnsum1, bnsq1, g1, b1, bns1, bnt1, NN, HDIM);

    // 5) feat2 = (hh0 + elu(bn(rst1))) @ fc2    [10000,256]x[256,32]
    {
        dim3 grid(1, (NN + 63)/64);
        mma_gemm<64,32,32,16,16,false,true><<<grid, 256>>>(
            NN, D2, HDIM, rst1, fc2, nullptr, hh0, bns1, bnt1, feat2);
    }
    // 6) layer-2 attention
    attn_coeff <<<(NN + 255)/256, 256>>>(feat2, al2, ar2, el2, er2, NN, H2, D2);
    gat_gather2<<<(NN*32 + 255)/256, 256>>>(rowptr, eidx, src, el2, er2, feat2, rst2);
    // 7) BN + ELU -> out
    bn_stats<<<157, 256>>>(rst2, bnsum2, bnsq2, NN, D2);
    bn_apply<<<(NN*D2 + 255)/256, 256>>>(rst2, bnsum2, bnsq2, g2, b2, out, NN, D2);

    (void)in_sizes; (void)n_in; (void)out_size;
}

// round 9
// speedup vs baseline: 4.3431x; 1.2283x over previous
#include <cuda_runtime.h>
#include <math.h>
#include <stdint.h>

#define NN    10000
#define NE    120000
#define IND   128
#define HDIM  256
#define H1    8
#define H2    1
#define D2    32

// ---------------- scratch (device globals; no allocations) ----------------
__device__ float    g_hh0  [NN*HDIM];
__device__ float    g_feat1[NN*HDIM];
__device__ float    g_rst1 [NN*HDIM];
__device__ float    g_el1  [NN*H1];
__device__ float    g_er1  [NN*H1];
__device__ float    g_feat2[NN*D2];
__device__ float    g_rst2 [NN*D2];
__device__ float    g_el2  [NN];
__device__ float    g_er2  [NN];
// BN accumulators packed: [sum1(256) | sq1(256) | sum2(32) | sq2(32)]
__device__ float    g_bnacc[2*HDIM + 2*D2];
__device__ float    g_bns1 [HDIM];
__device__ float    g_bnt1 [HDIM];
// CSR by destination
__device__ int      g_deg   [NN];
__device__ int      g_rowptr[NN+1];
__device__ int      g_cursor[NN];
__device__ int      g_eidx  [NE];

// ---------------- tf32 helpers ----------------
__device__ __forceinline__ uint32_t f2tf32(float f) {
    uint32_t u;
    asm("cvt.rna.tf32.f32 %0, %1;" : "=r"(u) : "f"(f));
    return u;
}

__device__ __forceinline__ void mma_tf32(float* d, const uint32_t* a, const uint32_t* b) {
    asm volatile(
        "mma.sync.aligned.m16n8k8.row.col.f32.tf32.tf32.f32 "
        "{%0,%1,%2,%3}, {%4,%5,%6,%7}, {%8,%9}, {%0,%1,%2,%3};\n"
        : "+f"(d[0]), "+f"(d[1]), "+f"(d[2]), "+f"(d[3])
        : "r"(a[0]), "r"(a[1]), "r"(a[2]), "r"(a[3]), "r"(b[0]), "r"(b[1]));
}

__device__ __forceinline__ float elu1(float y) { return (y > 0.f) ? y : expm1f(y); }

// ---------------- tf32 tensor-core GEMM, double-buffered ----------------
// C[M,N] = A'[M,K] @ B[K,N] (+bias)
// FUSE_BN: A'[i,c] = HH0[i,c] + elu(A[i,c]*bns[c] + bnt[c])
// ATTN=1: 8-head attention coeffs (WN must be 32): el/er[node*8+h] = sum_d C*al/ar
// ATTN=2: 1-head attention coeffs (BN=32, WN=16): el/er[node]
template<int BM, int BN, int BK, int WM, int WN, bool BIAS, bool FUSE_BN, int ATTN>
__global__ __launch_bounds__(256)
void mma_gemm(int M, int N, int K,
              const float* __restrict__ A,
              const float* __restrict__ B,
              const float* __restrict__ bias,
              const float* __restrict__ HH0,
              const float* __restrict__ bns,
              const float* __restrict__ bnt,
              const float* __restrict__ wl_g,
              const float* __restrict__ wr_g,
              float* __restrict__ el_out,
              float* __restrict__ er_out,
              float* __restrict__ C) {
    constexpr int WARPS_N = BN / WN;
    constexpr int FM = WM / 16;
    constexpr int FN = WN / 8;
    constexpr int AV = BM * BK / (4 * 256);
    constexpr int BV = BK * BN / (4 * 256);
    constexpr int AC = BK / 4;
    constexpr int BC = BN / 4;
    constexpr int APAD = BK + 4;   // A row stride (words): banks g*4+tig distinct
    constexpr int BPAD = BN + 8;   // B row stride (words): banks tig*8+g distinct
    constexpr int ASZ = BM * APAD;
    constexpr int BSZ = BK * BPAD;

    extern __shared__ __align__(16) uint32_t sm[];
    uint32_t* AsB = sm;             // [2][BM][APAD]
    uint32_t* BsB = sm + 2 * ASZ;   // [2][BK][BPAD]
    __shared__ float attn_el[64][2], attn_er[64][2];   // ATTN==2 only

    const int tid  = threadIdx.x;
    const int wid  = tid >> 5;
    const int lane = tid & 31;
    const int g    = lane >> 2;
    const int tig  = lane & 3;
    const int wm   = (wid / WARPS_N) * WM;
    const int wn   = (wid % WARPS_N) * WN;
    const int bm0  = blockIdx.y * BM;
    const int bn0  = blockIdx.x * BN;

    float acc[FM][FN][4];
    #pragma unroll
    for (int i = 0; i < FM; i++)
        #pragma unroll
        for (int j = 0; j < FN; j++)
            #pragma unroll
            for (int r = 0; r < 4; r++) acc[i][j][r] = 0.f;

    float4 aR[AV], bR[BV];

    auto loadA = [&](int k0) {
        #pragma unroll
        for (int i = 0; i < AV; i++) {
            int v = tid + i * 256;
            int r = v / AC, c4 = (v % AC) * 4;
            int gr = bm0 + r;
            float4 x = make_float4(0.f, 0.f, 0.f, 0.f);
            if (gr < M) {
                x = *(const float4*)&A[(long)gr * K + k0 + c4];
                if (FUSE_BN) {
                    int c = k0 + c4;
                    float4 hv = *(const float4*)&HH0[(long)gr * K + c];
                    x.x = hv.x + elu1(x.x * bns[c    ] + bnt[c    ]);
                    x.y = hv.y + elu1(x.y * bns[c + 1] + bnt[c + 1]);
                    x.z = hv.z + elu1(x.z * bns[c + 2] + bnt[c + 2]);
                    x.w = hv.w + elu1(x.w * bns[c + 3] + bnt[c + 3]);
                }
            }
            aR[i] = x;
        }
    };
    auto loadB = [&](int k0) {
        #pragma unroll
        for (int i = 0; i < BV; i++) {
            int v = tid + i * 256;
            int r = v / BC, c4 = (v % BC) * 4;
            bR[i] = *(const float4*)&B[(long)(k0 + r) * N + bn0 + c4];
        }
    };
    auto stsA = [&](int buf) {
        #pragma unroll
        for (int i = 0; i < AV; i++) {
            int v = tid + i * 256;
            int r = v / AC, c4 = (v % AC) * 4;
            uint4 u;
            u.x = f2tf32(aR[i].x); u.y = f2tf32(aR[i].y);
            u.z = f2tf32(aR[i].z); u.w = f2tf32(aR[i].w);
            *(uint4*)&AsB[buf * ASZ + r * APAD + c4] = u;
        }
    };
    auto stsB = [&](int buf) {
        #pragma unroll
        for (int i = 0; i < BV; i++) {
            int v = tid + i * 256;
            int r = v / BC, c4 = (v % BC) * 4;
            uint4 u;
            u.x = f2tf32(bR[i].x); u.y = f2tf32(bR[i].y);
            u.z = f2tf32(bR[i].z); u.w = f2tf32(bR[i].w);
            *(uint4*)&BsB[buf * BSZ + r * BPAD + c4] = u;
        }
    };

    loadA(0);
    loadB(0);
    stsA(0);
    stsB(0);
    __syncthreads();

    const int KT = K / BK;
    for (int kt = 0; kt < KT; kt++) {
        int cur = kt & 1;
        if (kt + 1 < KT) {
            loadA((kt + 1) * BK);
            loadB((kt + 1) * BK);
        }
        const uint32_t* Asc = AsB + cur * ASZ;
        const uint32_t* Bsc = BsB + cur * BSZ;
        #pragma unroll
        for (int k8 = 0; k8 < BK; k8 += 8) {
            uint32_t af[FM][4], bf[FN][2];
            #pragma unroll
            for (int fm = 0; fm < FM; fm++) {
                int m = wm + fm * 16 + g;
                af[fm][0] = Asc[m * APAD + k8 + tig];
                af[fm][1] = Asc[(m + 8) * APAD + k8 + tig];
                af[fm][2] = Asc[m * APAD + k8 + tig + 4];
                af[fm][3] = Asc[(m + 8) * APAD + k8 + tig + 4];
            }
            #pragma unroll
            for (int fn = 0; fn < FN; fn++) {
                int n = wn + fn * 8 + g;
                bf[fn][0] = Bsc[(k8 + tig) * BPAD + n];
                bf[fn][1] = Bsc[(k8 + tig + 4) * BPAD + n];
            }
            #pragma unroll
            for (int fm = 0; fm < FM; fm++)
                #pragma unroll
                for (int fn = 0; fn < FN; fn++)
                    mma_tf32(acc[fm][fn], af[fm], bf[fn]);
        }
        if (kt + 1 < KT) {
            stsA(cur ^ 1);
            stsB(cur ^ 1);
            __syncthreads();
        }
    }

    // C store
    #pragma unroll
    for (int fm = 0; fm < FM; fm++) {
        int r0 = bm0 + wm + fm * 16 + g;
        #pragma unroll
        for (int fn = 0; fn < FN; fn++) {
            int cb = bn0 + wn + fn * 8 + 2 * tig;
            float bx = 0.f, by = 0.f;
            if (BIAS) { bx = bias[cb]; by = bias[cb + 1]; }
            if (r0 < M) {
                float2 v = make_float2(acc[fm][fn][0] + bx, acc[fm][fn][1] + by);
                *(float2*)&C[(long)r0 * N + cb] = v;
            }
            if (r0 + 8 < M) {
                float2 v = make_float2(acc[fm][fn][2] + bx, acc[fm][fn][3] + by);
                *(float2*)&C[(long)(r0 + 8) * N + cb] = v;
            }
        }
    }

    // fused attention coefficients (both ATTN GEMMs have BIAS=false, acc is final)
    if (ATTN == 1) {
        // WN == 32: each warp owns exactly one head
        int h = (bn0 + wn) >> 5;
        float wlv[FN][2], wrv[FN][2];
        #pragma unroll
        for (int fn = 0; fn < FN; fn++) {
            int d = (fn * 8 + 2 * tig);   // wn multiple of 32
            wlv[fn][0] = wl_g[h * 32 + d];     wlv[fn][1] = wl_g[h * 32 + d + 1];
            wrv[fn][0] = wr_g[h * 32 + d];     wrv[fn][1] = wr_g[h * 32 + d + 1];
        }
        #pragma unroll
        for (int fm = 0; fm < FM; fm++) {
            float elA = 0.f, erA = 0.f, elB = 0.f, erB = 0.f;
            #pragma unroll
            for (int fn = 0; fn < FN; fn++) {
                elA += acc[fm][fn][0] * wlv[fn][0] + acc[fm][fn][1] * wlv[fn][1];
                elB += acc[fm][fn][2] * wlv[fn][0] + acc[fm][fn][3] * wlv[fn][1];
                erA += acc[fm][fn][0] * wrv[fn][0] + acc[fm][fn][1] * wrv[fn][1];
                erB += acc[fm][fn][2] * wrv[fn][0] + acc[fm][fn][3] * wrv[fn][1];
            }
            #pragma unroll
            for (int off = 1; off <= 2; off <<= 1) {
                elA += __shfl_xor_sync(0xffffffffu, elA, off);
                elB += __shfl_xor_sync(0xffffffffu, elB, off);
                erA += __shfl_xor_sync(0xffffffffu, erA, off);
                erB += __shfl_xor_sync(0xffffffffu, erB, off);
            }
            int gr = bm0 + wm + fm * 16 + g;
            if (tig == 0) {
                if (gr < M)     { el_out[gr * 8 + h] = elA;       er_out[gr * 8 + h] = erA; }
                if (gr + 8 < M) { el_out[(gr + 8) * 8 + h] = elB; er_out[(gr + 8) * 8 + h] = erB; }
            }
        }
    }
    if (ATTN == 2) {
        // BN == 32, WN == 16, FM == 1, single head
        float wlv[FN][2], wrv[FN][2];
        #pragma unroll
        for (int fn = 0; fn < FN; fn++) {
            int d = wn + fn * 8 + 2 * tig;
            wlv[fn][0] = wl_g[d];  wlv[fn][1] = wl_g[d + 1];
            wrv[fn][0] = wr_g[d];  wrv[fn][1] = wr_g[d + 1];
        }
        float elA = 0.f, erA = 0.f, elB = 0.f, erB = 0.f;
        #pragma unroll
        for (int fn = 0; fn < FN; fn++) {
            elA += acc[0][fn][0] * wlv[fn][0] + acc[0][fn][1] * wlv[fn][1];
            elB += acc[0][fn][2] * wlv[fn][0] + acc[0][fn][3] * wlv[fn][1];
            erA += acc[0][fn][0] * wrv[fn][0] + acc[0][fn][1] * wrv[fn][1];
            erB += acc[0][fn][2] * wrv[fn][0] + acc[0][fn][3] * wrv[fn][1];
        }
        #pragma unroll
        for (int off = 1; off <= 2; off <<= 1) {
            elA += __shfl_xor_sync(0xffffffffu, elA, off);
            elB += __shfl_xor_sync(0xffffffffu, elB, off);
            erA += __shfl_xor_sync(0xffffffffu, erA, off);
            erB += __shfl_xor_sync(0xffffffffu, erB, off);
        }
        int wcol = wn >> 4;
        if (tig == 0) {
            attn_el[wm + g][wcol]     = elA;  attn_er[wm + g][wcol]     = erA;
            attn_el[wm + 8 + g][wcol] = elB;  attn_er[wm + 8 + g][wcol] = erB;
        }
        __syncthreads();
        if (tid < 64) {
            int gr = bm0 + tid;
            if (gr < M) {
                el_out[gr] = attn_el[tid][0] + attn_el[tid][1];
                er_out[gr] = attn_er[tid][0] + attn_er[tid][1];
            }
        }
    }
}

// ---------------- CSR construction ----------------
__global__ void csr_count(const int* __restrict__ dst, int* __restrict__ deg, int E) {
    int e = blockIdx.x * blockDim.x + threadIdx.x;
    if (e < E) atomicAdd(&deg[dst[e]], 1);
}

__global__ void csr_scan(const int* __restrict__ deg, int* __restrict__ rowptr,
                         int* __restrict__ cursor) {
    __shared__ int part[1024];
    int tid = threadIdx.x;
    const int PER = (NN + 1023) / 1024;  // 10
    int base = tid * PER;
    int local[PER];
    int s = 0;
    #pragma unroll
    for (int i = 0; i < PER; i++) {
        int idx = base + i;
        local[i] = (idx < NN) ? deg[idx] : 0;
        s += local[i];
    }
    part[tid] = s;
    __syncthreads();
    for (int off = 1; off < 1024; off <<= 1) {
        int v = (tid >= off) ? part[tid - off] : 0;
        __syncthreads();
        part[tid] += v;
        __syncthreads();
    }
    int excl = part[tid] - s;
    #pragma unroll
    for (int i = 0; i < PER; i++) {
        int idx = base + i;
        if (idx < NN) { rowptr[idx] = excl; cursor[idx] = excl; }
        excl += local[i];
    }
    if (tid == 1023) rowptr[NN] = excl;
}

__global__ void csr_fill(const int* __restrict__ dst, int* __restrict__ cursor,
                         int* __restrict__ eidx, int E) {
    int e = blockIdx.x * blockDim.x + threadIdx.x;
    if (e >= E) return;
    int p = atomicAdd(&cursor[dst[e]], 1);
    eidx[p] = e;
}

__device__ __forceinline__ float leaky(float x) { return (x >= 0.f) ? x : 0.2f * x; }

// ---------------- gather aggregation, layer 1 ----------------
__global__ void gat_gather1(const int* __restrict__ rowptr, const int* __restrict__ eidx,
                            const int* __restrict__ src,
                            const float* __restrict__ el,    // [N,8]
                            const float* __restrict__ er,    // [N,8]
                            const float* __restrict__ feat,  // [N,256]
                            float* __restrict__ rst) {
    int node = blockIdx.x * (blockDim.x >> 5) + (threadIdx.x >> 5);
    int lane = threadIdx.x & 31;
    if (node >= NN) return;
    int s0 = rowptr[node], deg = rowptr[node+1] - s0;

    const float4* erp = (const float4*)(er + (long)node*8);
    float4 er0 = erp[0], er1v = erp[1];
    float erh[8] = {er0.x, er0.y, er0.z, er0.w, er1v.x, er1v.y, er1v.z, er1v.w};

    float m[8], s[8], acc[8];
    #pragma unroll
    for (int h = 0; h < 8; h++) { m[h] = -3.0e38f; s[h] = 0.f; acc[h] = 0.f; }

    for (int base = 0; base < deg; base += 32) {
        int cnt = min(32, deg - base);
        int sv = 0;
        float l[8];
        #pragma unroll
        for (int h = 0; h < 8; h++) l[h] = -3.0e38f;
        if (lane < cnt) {
            int e = eidx[s0 + base + lane];
            sv = src[e];
            const float4* lp = (const float4*)(el + (long)sv*8);
            float4 a = lp[0], b = lp[1];
            l[0] = leaky(a.x + erh[0]); l[1] = leaky(a.y + erh[1]);
            l[2] = leaky(a.z + erh[2]); l[3] = leaky(a.w + erh[3]);
            l[4] = leaky(b.x + erh[4]); l[5] = leaky(b.y + erh[5]);
            l[6] = leaky(b.z + erh[6]); l[7] = leaky(b.w + erh[7]);
        }
        float p[8];
        #pragma unroll
        for (int h = 0; h < 8; h++) {
            float cm = l[h];
            #pragma unroll
            for (int off = 16; off; off >>= 1)
                cm = fmaxf(cm, __shfl_xor_sync(0xffffffffu, cm, off));
            float nm = fmaxf(m[h], cm);
            float r = __expf(m[h] - nm);
            s[h]  *= r;
            acc[h] *= r;
            p[h] = __expf(l[h] - nm);
            float ps = p[h];
            #pragma unroll
            for (int off = 16; off; off >>= 1)
                ps += __shfl_xor_sync(0xffffffffu, ps, off);
            s[h] += ps;
            m[h] = nm;
        }
        for (int j = 0; j < cnt; j++) {
            int sn = __shfl_sync(0xffffffffu, sv, j);
            const float* fp = feat + (long)sn*HDIM + lane;
            #pragma unroll
            for (int h = 0; h < 8; h++) {
                float a = __shfl_sync(0xffffffffu, p[h], j);
                acc[h] = fmaf(a, fp[h*32], acc[h]);
            }
        }
    }
    float* rp = rst + (long)node*HDIM + lane;
    #pragma unroll
    for (int h = 0; h < 8; h++) rp[h*32] = acc[h] / (s[h] + 1e-16f);
}

// ---------------- gather aggregation, layer 2 (1 head) ----------------
__global__ void gat_gather2(const int* __restrict__ rowptr, const int* __restrict__ eidx,
                            const int* __restrict__ src,
                            const float* __restrict__ el,
                            const float* __restrict__ er,
                            const float* __restrict__ feat,  // [N,32]
                            float* __restrict__ rst) {
    int node = blockIdx.x * (blockDim.x >> 5) + (threadIdx.x >> 5);
    int lane = threadIdx.x & 31;
    if (node >= NN) return;
    int s0 = rowptr[node], deg = rowptr[node+1] - s0;
    float ern = er[node];

    float m = -3.0e38f, s = 0.f, acc = 0.f;
    for (int base = 0; base < deg; base += 32) {
        int cnt = min(32, deg - base);
        int sv = 0;
        float l = -3.0e38f;
        if (lane < cnt) {
            int e = eidx[s0 + base + lane];
            sv = src[e];
            l = leaky(el[sv] + ern);
        }
        float cm = l;
        #pragma unroll
        for (int off = 16; off; off >>= 1)
            cm = fmaxf(cm, __shfl_xor_sync(0xffffffffu, cm, off));
        float nm = fmaxf(m, cm);
        float r = __expf(m - nm);
        s *= r; acc *= r;
        float p = __expf(l - nm);
        float ps = p;
        #pragma unroll
        for (int off = 16; off; off >>= 1)
            ps += __shfl_xor_sync(0xffffffffu, ps, off);
        s += ps;
        m = nm;
        for (int j = 0; j < cnt; j++) {
            int sn = __shfl_sync(0xffffffffu, sv, j);
            float a = __shfl_sync(0xffffffffu, p, j);
            acc = fmaf(a, feat[(long)sn*D2 + lane], acc);
        }
    }
    rst[(long)node*D2 + lane] = acc / (s + 1e-16f);
}

// ---------------- BN batch stats ----------------
__global__ void bn_stats(const float* __restrict__ x,
                         float* __restrict__ gsum, float* __restrict__ gsq,
                         int n, int C) {
    int tid = threadIdx.x;
    int c  = tid % C;
    int rl = tid / C;
    int L  = blockDim.x / C;
    int rows = (n + gridDim.x - 1) / gridDim.x;
    int r0 = blockIdx.x * rows;
    int r1 = min(n, r0 + rows);
    float s = 0.f, q = 0.f;
    for (int r = r0 + rl; r < r1; r += L) {
        float v = x[(long)r*C + c];
        s += v; q += v*v;
    }
    __shared__ float ss[256], sq[256];
    ss[tid] = s; sq[tid] = q;
    __syncthreads();
    if (rl == 0) {
        for (int l = 1; l < L; l++) { s += ss[l*C + c]; q += sq[l*C + c]; }
        atomicAdd(&gsum[c], s);
        atomicAdd(&gsq[c],  q);
    }
}

// ---------------- BN finalize ----------------
__global__ void bn_finalize(const float* __restrict__ gsum, const float* __restrict__ gsq,
                            const float* __restrict__ g, const float* __restrict__ b,
                            float* __restrict__ sc, float* __restrict__ sh, int n, int C) {
    int c = blockIdx.x * blockDim.x + threadIdx.x;
    if (c >= C) return;
    float inv_n = 1.f / (float)n;
    float mu  = gsum[c] * inv_n;
    float var = gsq[c] * inv_n - mu*mu;
    float rstd = rsqrtf(var + 1e-5f);
    float s = g[c] * rstd;
    sc[c] = s;
    sh[c] = b[c] - mu * s;
}

// ---------------- BN apply + ELU (layer 2 -> output) ----------------
__global__ void bn_apply(const float* __restrict__ x,
                         const float* __restrict__ gsum, const float* __restrict__ gsq,
                         const float* __restrict__ g, const float* __restrict__ b,
                         float* __restrict__ out, int n, int C) {
    int idx = blockIdx.x * blockDim.x + threadIdx.x;
    if (idx >= n * C) return;
    int c = idx % C;
    float inv_n = 1.f / (float)n;
    float mu  = gsum[c] * inv_n;
    float var = gsq[c] * inv_n - mu*mu;
    float y = g[c] * (x[idx] - mu) * rsqrtf(var + 1e-5f) + b[c];
    out[idx] = elu1(y);
}

// ---------------- host launch ----------------
static inline void* sym(const void* s) {
    void* p = nullptr;
    cudaGetSymbolAddress(&p, s);
    return p;
}

// smem sizes (bytes) for the GEMM configs
#define SMEM_G12 ((2*64*(32+4) + 2*32*(128+8)) * 4)   // 53248
#define SMEM_G3  ((2*64*(32+4) + 2*32*(32+8))  * 4)   // 28672

extern "C" void kernel_launch(void* const* d_in, const int* in_sizes, int n_in,
                              void* d_out, int out_size) {
    const float* h     = (const float*)d_in[0];
    const int*   src   = (const int*)  d_in[2];
    const int*   dst   = (const int*)  d_in[3];
    const float* W_emb = (const float*)d_in[4];
    const float* b_emb = (const float*)d_in[5];
    const float* fc1   = (const float*)d_in[18];
    const float* al1   = (const float*)d_in[19];
    const float* ar1   = (const float*)d_in[20];
    const float* g1    = (const float*)d_in[21];
    const float* b1    = (const float*)d_in[22];
    const float* fc2   = (const float*)d_in[23];
    const float* al2   = (const float*)d_in[24];
    const float* ar2   = (const float*)d_in[25];
    const float* g2    = (const float*)d_in[26];
    const float* b2    = (const float*)d_in[27];
    float* out = (float*)d_out;

    float* hh0   = (float*)sym(g_hh0);
    float* feat1 = (float*)sym(g_feat1);
    float* rst1  = (float*)sym(g_rst1);
    float* el1   = (float*)sym(g_el1);
    float* er1   = (float*)sym(g_er1);
    float* feat2 = (float*)sym(g_feat2);
    float* rst2  = (float*)sym(g_rst2);
    float* el2   = (float*)sym(g_el2);
    float* er2   = (float*)sym(g_er2);
    float* bnacc = (float*)sym(g_bnacc);
    float* bns1  = (float*)sym(g_bns1);
    float* bnt1  = (float*)sym(g_bnt1);
    int*   deg   = (int*)  sym(g_deg);
    int*   rowptr= (int*)  sym(g_rowptr);
    int*   cursor= (int*)  sym(g_cursor);
    int*   eidx  = (int*)  sym(g_eidx);

    float* bnsum1 = bnacc;
    float* bnsq1  = bnacc + HDIM;
    float* bnsum2 = bnacc + 2*HDIM;
    float* bnsq2  = bnacc + 2*HDIM + D2;

    // opt in to >48KB dynamic smem for the 128-wide GEMM instantiations
    cudaFuncSetAttribute(mma_gemm<64,128,32,32,32,true, false,0>,
                         cudaFuncAttributeMaxDynamicSharedMemorySize, SMEM_G12);
    cudaFuncSetAttribute(mma_gemm<64,128,32,32,32,false,false,1>,
                         cudaFuncAttributeMaxDynamicSharedMemorySize, SMEM_G12);

    // zero accumulators (graph replays must be deterministic)
    cudaMemsetAsync(deg,   0, sizeof(int)*NN);
    cudaMemsetAsync(bnacc, 0, sizeof(float)*(2*HDIM + 2*D2));

    // CSR by destination
    csr_count<<<(NE + 255)/256, 256>>>(dst, deg, NE);
    csr_scan <<<1, 1024>>>(deg, rowptr, cursor);
    csr_fill <<<(NE + 255)/256, 256>>>(dst, cursor, eidx, NE);

    // 1) hh0 = h @ W_emb + b_emb
    {
        dim3 grid(HDIM/128, (NN + 63)/64);
        mma_gemm<64,128,32,32,32,true,false,0><<<grid, 256, SMEM_G12>>>(
            NN, HDIM, IND, h, W_emb, b_emb,
            nullptr, nullptr, nullptr, nullptr, nullptr, nullptr, nullptr, hh0);
    }
    // 2) feat1 = hh0 @ fc1, fused el1/er1
    {
        dim3 grid(HDIM/128, (NN + 63)/64);
        mma_gemm<64,128,32,32,32,false,false,1><<<grid, 256, SMEM_G12>>>(
            NN, HDIM, HDIM, hh0, fc1, nullptr,
            nullptr, nullptr, nullptr, al1, ar1, el1, er1, feat1);
    }
    // 3) gather aggregation (single pass, online softmax, inline logits)
    gat_gather1<<<(NN*32 + 255)/256, 256>>>(rowptr, eidx, src, el1, er1, feat1, rst1);
    // 4) BN stats + finalize (apply fused into next GEMM's A-load)
    bn_stats   <<<157, 256>>>(rst1, bnsum1, bnsq1, NN, HDIM);
    bn_finalize<<<1, HDIM>>>(bnsum1, bnsq1, g1, b1, bns1, bnt1, NN, HDIM);

    // 5) feat2 = (hh0 + elu(bn(rst1))) @ fc2, fused el2/er2
    {
        dim3 grid(1, (NN + 63)/64);
        mma_gemm<64,32,32,16,16,false,true,2><<<grid, 256, SMEM_G3>>>(
            NN, D2, HDIM, rst1, fc2, nullptr,
            hh0, bns1, bnt1, al2, ar2, el2, er2, feat2);
    }
    // 6) layer-2 gather
    gat_gather2<<<(NN*32 + 255)/256, 256>>>(rowptr, eidx, src, el2, er2, feat2, rst2);
    // 7) BN + ELU -> out
    bn_stats<<<157, 256>>>(rst2, bnsum2, bnsq2, NN, D2);
    bn_apply<<<(NN*D2 + 255)/256, 256>>>(rst2, bnsum2, bnsq2, g2, b2, out, NN, D2);

    (void)in_sizes; (void)n_in; (void)out_size;
}